// round 5
// baseline (speedup 1.0000x reference)
#include <cuda_runtime.h>

// Shapes (fixed by the problem)
#define BT   768    // B*T = 32*24
#define NN   512    // nodes
#define DIN  64
#define HID  128
#define EMB  16

// ---------------- scratch (__device__ globals: sanctioned, no allocs) ----------
__device__ float g_Q[EMB * DIN * HID];     // Q[d][j][o] = sum_i W1[j,i]*pool_spa[d,i,o]
__device__ float g_CB[EMB * HID];          // CB[d][o]   = b1@pool_spa[d] + bias_pool_spa[d]
__device__ float g_Wc[NN * DIN * HID];     // Wc[n][j][o] = sum_d node_eb[n,d]*Q[d][j][o]
__device__ float g_bspa[NN * HID];         // combined spatial bias
__device__ float g_Wt[BT * HID * HID];     // temporal weights per (b,t)
__device__ float g_btem[BT * HID];         // temporal bias per (b,t)
__device__ float g_outspa[BT * NN * HID];  // spatial activations [bt][n][128]

__device__ __forceinline__ float lrelu(float x) { return x >= 0.0f ? x : 0.01f * x; }

// packed f32x2 helpers (FFMA2: 2x fp32 FMA throughput on sm_103a)
__device__ __forceinline__ unsigned long long pk2(float x) {
    unsigned long long r;
    asm("mov.b64 %0, {%1, %1};" : "=l"(r) : "f"(x));
    return r;
}
__device__ __forceinline__ unsigned long long pkf2(float x, float y) {
    unsigned long long r;
    asm("mov.b64 %0, {%1, %2};" : "=l"(r) : "f"(x), "f"(y));
    return r;
}
__device__ __forceinline__ void fma2(unsigned long long& c, unsigned long long a,
                                     unsigned long long b) {
    asm("fma.rn.f32x2 %0, %1, %2, %0;" : "+l"(c) : "l"(a), "l"(b));
}
__device__ __forceinline__ float2 upk(unsigned long long v) {
    float2 f;
    asm("mov.b64 {%0, %1}, %2;" : "=f"(f.x), "=f"(f.y) : "l"(v));
    return f;
}

// ---------------- K0: Q[d] = W1 @ pool_spa[d], CB[d] = b1@pool_spa[d]+bias_pool_spa[d]
__global__ void k_Q(const float* __restrict__ W1, const float* __restrict__ b1,
                    const float* __restrict__ Pspa, const float* __restrict__ Bspa) {
    __shared__ float sW1[DIN * HID];
    int d = blockIdx.x, t = threadIdx.x;
    for (int l = t; l < DIN * HID; l += 256) sW1[l] = W1[l];
    __syncthreads();
    int o = t & 127, jh = t >> 7;  // 2 halves of j-range
    const float* P = Pspa + d * HID * HID;
    float acc[32];
#pragma unroll
    for (int j = 0; j < 32; ++j) acc[j] = 0.f;
    for (int i = 0; i < HID; ++i) {
        float p = P[i * HID + o];
#pragma unroll
        for (int j = 0; j < 32; ++j) acc[j] += sW1[(jh * 32 + j) * HID + i] * p;
    }
#pragma unroll
    for (int j = 0; j < 32; ++j) g_Q[(d * DIN + jh * 32 + j) * HID + o] = acc[j];
    if (jh == 0) {
        float cb = Bspa[d * HID + o];
        for (int i = 0; i < HID; ++i) cb += b1[i] * P[i * HID + o];
        g_CB[d * HID + o] = cb;
    }
}

// ---------------- K1: Wc[n] = sum_d node_eb[n,d] * Q[d] (elementwise over 8192)
__global__ void k_Wc(const float* __restrict__ node_eb) {
    __shared__ float sQ[EMB][256];
    __shared__ float sNe[256 * EMB];
    int t = threadIdx.x;
    int base = blockIdx.x * 256;  // 32 blocks cover 8192 elems
    for (int l = t; l < EMB * 256; l += 256) {
        int d = l >> 8, e = l & 255;
        sQ[d][e] = g_Q[d * (DIN * HID) + base + e];
    }
    float q[EMB];
    __syncthreads();
#pragma unroll
    for (int d = 0; d < EMB; ++d) q[d] = sQ[d][t];
    for (int nc = 0; nc < 2; ++nc) {
        __syncthreads();
        for (int l = t; l < 256 * EMB; l += 256) sNe[l] = node_eb[nc * 256 * EMB + l];
        __syncthreads();
        for (int n = 0; n < 256; ++n) {
            float acc = 0.f;
#pragma unroll
            for (int d = 0; d < EMB; ++d) acc += sNe[n * EMB + d] * q[d];
            g_Wc[(nc * 256 + n) * (DIN * HID) + base + t] = acc;
        }
    }
}

// ---------------- K2: Wt[bt] = sum_d time_eb[bt,d] * pool_tem[d]
__global__ void k_Wt(const float* __restrict__ time_eb, const float* __restrict__ Ptem) {
    __shared__ float sP[EMB][256];
    __shared__ float sTe[128 * EMB];
    int t = threadIdx.x;
    int base = blockIdx.x * 256;  // 64 blocks cover 16384 elems
    for (int l = t; l < EMB * 256; l += 256) {
        int d = l >> 8, e = l & 255;
        sP[d][e] = Ptem[d * (HID * HID) + base + e];
    }
    float q[EMB];
    __syncthreads();
#pragma unroll
    for (int d = 0; d < EMB; ++d) q[d] = sP[d][t];
    for (int c = 0; c < 6; ++c) {  // 768 bt in chunks of 128
        __syncthreads();
        for (int l = t; l < 128 * EMB; l += 256) sTe[l] = time_eb[c * 128 * EMB + l];
        __syncthreads();
        for (int r = 0; r < 128; ++r) {
            float acc = 0.f;
#pragma unroll
            for (int d = 0; d < EMB; ++d) acc += sTe[r * EMB + d] * q[d];
            g_Wt[(size_t)(c * 128 + r) * (HID * HID) + base + t] = acc;
        }
    }
}

// ---------------- K3: biases (spatial combined + temporal)
__global__ void k_bias(const float* __restrict__ node_eb, const float* __restrict__ time_eb,
                       const float* __restrict__ Btem) {
    int t = threadIdx.x;
    int b = blockIdx.x;
    if (b < NN) {
        float acc = 0.f;
#pragma unroll
        for (int d = 0; d < EMB; ++d) acc += node_eb[b * EMB + d] * g_CB[d * HID + t];
        g_bspa[b * HID + t] = acc;
    } else {
        int bt = b - NN;
        float acc = 0.f;
#pragma unroll
        for (int d = 0; d < EMB; ++d) acc += time_eb[bt * EMB + d] * Btem[d * HID + t];
        g_btem[bt * HID + t] = acc;
    }
}

// ---------------- K4: spatial GEMM  out_spa = LReLU(eb @ Wc[n] + bspa[n])
// Block: 1 node x 128 bt rows x 128 cols, K=64 in 2 chunks of 32. 256 threads,
// micro-tile 8 rows x 8 cols per thread; row-pairs packed into f32x2 lanes.
__global__ __launch_bounds__(256, 2) void k_spatial(const float* __restrict__ eb) {
    __shared__ float AsT[32][132];  // [k][row], row-pad keeps 16B alignment, conflict-light
    __shared__ float Bs[32][128];   // [k][col]
    int n = blockIdx.y;
    int bt0 = blockIdx.x * 128;
    int t = threadIdx.x;
    int tc = t & 15, tr = t >> 4;
    unsigned long long acc[4][8];
#pragma unroll
    for (int i = 0; i < 4; ++i)
#pragma unroll
        for (int j = 0; j < 8; ++j) acc[i][j] = 0ull;
    const float* Wc = g_Wc + n * (DIN * HID);

    for (int k0 = 0; k0 < DIN; k0 += 32) {
#pragma unroll
        for (int l = t; l < 1024; l += 256) {  // A: 128 rows x 32 k (k-major store)
            int r = l >> 3, c4 = l & 7;
            float4 v = *(const float4*)(eb + ((bt0 + r) * NN + n) * DIN + k0 + c4 * 4);
            int kk = c4 * 4;
            AsT[kk + 0][r] = v.x; AsT[kk + 1][r] = v.y;
            AsT[kk + 2][r] = v.z; AsT[kk + 3][r] = v.w;
        }
#pragma unroll
        for (int l = t; l < 1024; l += 256) {  // B: 32 k-rows x 128 cols
            int kk = l >> 5, c4 = l & 31;
            *(float4*)&Bs[kk][c4 * 4] = *(const float4*)(Wc + (k0 + kk) * HID + c4 * 4);
        }
        __syncthreads();
#pragma unroll 8
        for (int k = 0; k < 32; ++k) {
            float4 a0 = *(const float4*)&AsT[k][tr * 8];
            float4 a1 = *(const float4*)&AsT[k][tr * 8 + 4];
            unsigned long long ap0 = pkf2(a0.x, a0.y);
            unsigned long long ap1 = pkf2(a0.z, a0.w);
            unsigned long long ap2 = pkf2(a1.x, a1.y);
            unsigned long long ap3 = pkf2(a1.z, a1.w);
            float4 b0 = *(const float4*)&Bs[k][tc * 4];
            float4 b1v = *(const float4*)&Bs[k][64 + tc * 4];
            unsigned long long bp[8] = {pk2(b0.x),  pk2(b0.y),  pk2(b0.z),  pk2(b0.w),
                                        pk2(b1v.x), pk2(b1v.y), pk2(b1v.z), pk2(b1v.w)};
#pragma unroll
            for (int c = 0; c < 8; ++c) {
                fma2(acc[0][c], ap0, bp[c]);
                fma2(acc[1][c], ap1, bp[c]);
                fma2(acc[2][c], ap2, bp[c]);
                fma2(acc[3][c], ap3, bp[c]);
            }
        }
        __syncthreads();
    }
    // epilogue: +bias, LeakyReLU, store out_spa[bt][n][o]
    float4 bcA = *(const float4*)(g_bspa + n * HID + tc * 4);
    float4 bcB = *(const float4*)(g_bspa + n * HID + 64 + tc * 4);
    float bias[8] = {bcA.x, bcA.y, bcA.z, bcA.w, bcB.x, bcB.y, bcB.z, bcB.w};
#pragma unroll
    for (int rp = 0; rp < 4; ++rp) {
        float v0[8], v1[8];
#pragma unroll
        for (int c = 0; c < 8; ++c) {
            float2 f = upk(acc[rp][c]);
            v0[c] = lrelu(f.x + bias[c]);
            v1[c] = lrelu(f.y + bias[c]);
        }
        int r = tr * 8 + rp * 2;
        float* d0 = g_outspa + (size_t)((bt0 + r) * NN + n) * HID;
        float* d1 = d0 + (size_t)NN * HID;
        *(float4*)(d0 + tc * 4)      = make_float4(v0[0], v0[1], v0[2], v0[3]);
        *(float4*)(d0 + 64 + tc * 4) = make_float4(v0[4], v0[5], v0[6], v0[7]);
        *(float4*)(d1 + tc * 4)      = make_float4(v1[0], v1[1], v1[2], v1[3]);
        *(float4*)(d1 + 64 + tc * 4) = make_float4(v1[4], v1[5], v1[6], v1[7]);
    }
}

// ---------------- K5: temporal GEMM fused with LReLU + final 128->2 projection
// Block: 1 (b,t) x 128 n-rows x 128 cols, K=128 in 4 chunks of 32.
__global__ __launch_bounds__(256, 2) void k_temporal(const float* __restrict__ W3,
                                                     const float* __restrict__ b3,
                                                     float* __restrict__ out) {
    __shared__ float AsT[32][132];
    __shared__ float Bs[32][128];
    int bt = blockIdx.y;
    int n0 = blockIdx.x * 128;
    int t = threadIdx.x;
    int tc = t & 15, tr = t >> 4;
    unsigned long long acc[4][8];
#pragma unroll
    for (int i = 0; i < 4; ++i)
#pragma unroll
        for (int j = 0; j < 8; ++j) acc[i][j] = 0ull;
    const float* A = g_outspa + (size_t)bt * NN * HID;
    const float* W = g_Wt + (size_t)bt * HID * HID;

    for (int k0 = 0; k0 < HID; k0 += 32) {
#pragma unroll
        for (int l = t; l < 1024; l += 256) {
            int r = l >> 3, c4 = l & 7;
            float4 v = *(const float4*)(A + (n0 + r) * HID + k0 + c4 * 4);
            int kk = c4 * 4;
            AsT[kk + 0][r] = v.x; AsT[kk + 1][r] = v.y;
            AsT[kk + 2][r] = v.z; AsT[kk + 3][r] = v.w;
        }
#pragma unroll
        for (int l = t; l < 1024; l += 256) {
            int kk = l >> 5, c4 = l & 31;
            *(float4*)&Bs[kk][c4 * 4] = *(const float4*)(W + (k0 + kk) * HID + c4 * 4);
        }
        __syncthreads();
#pragma unroll 8
        for (int k = 0; k < 32; ++k) {
            float4 a0 = *(const float4*)&AsT[k][tr * 8];
            float4 a1 = *(const float4*)&AsT[k][tr * 8 + 4];
            unsigned long long ap0 = pkf2(a0.x, a0.y);
            unsigned long long ap1 = pkf2(a0.z, a0.w);
            unsigned long long ap2 = pkf2(a1.x, a1.y);
            unsigned long long ap3 = pkf2(a1.z, a1.w);
            float4 b0 = *(const float4*)&Bs[k][tc * 4];
            float4 b1v = *(const float4*)&Bs[k][64 + tc * 4];
            unsigned long long bp[8] = {pk2(b0.x),  pk2(b0.y),  pk2(b0.z),  pk2(b0.w),
                                        pk2(b1v.x), pk2(b1v.y), pk2(b1v.z), pk2(b1v.w)};
#pragma unroll
            for (int c = 0; c < 8; ++c) {
                fma2(acc[0][c], ap0, bp[c]);
                fma2(acc[1][c], ap1, bp[c]);
                fma2(acc[2][c], ap2, bp[c]);
                fma2(acc[3][c], ap3, bp[c]);
            }
        }
        __syncthreads();
    }
    // epilogue: +bias_tem, LReLU, project to 2 outs via W3, reduce over the 16 tc lanes
    float4 btA = *(const float4*)(g_btem + bt * HID + tc * 4);
    float4 btB = *(const float4*)(g_btem + bt * HID + 64 + tc * 4);
    float bias[8] = {btA.x, btA.y, btA.z, btA.w, btB.x, btB.y, btB.z, btB.w};
    float w30[8], w31[8];
    {
        float4 u0 = *(const float4*)(W3 + tc * 8);        // cols tc*4, tc*4+1
        float4 u1 = *(const float4*)(W3 + tc * 8 + 4);    // cols tc*4+2, tc*4+3
        float4 u2 = *(const float4*)(W3 + 128 + tc * 8);  // cols 64+tc*4 ...
        float4 u3 = *(const float4*)(W3 + 128 + tc * 8 + 4);
        w30[0] = u0.x; w31[0] = u0.y; w30[1] = u0.z; w31[1] = u0.w;
        w30[2] = u1.x; w31[2] = u1.y; w30[3] = u1.z; w31[3] = u1.w;
        w30[4] = u2.x; w31[4] = u2.y; w30[5] = u2.z; w31[5] = u2.w;
        w30[6] = u3.x; w31[6] = u3.y; w30[7] = u3.z; w31[7] = u3.w;
    }
    float bb0 = b3[0], bb1 = b3[1];
#pragma unroll
    for (int rp = 0; rp < 4; ++rp) {
        float p00 = 0.f, p01 = 0.f, p10 = 0.f, p11 = 0.f;
#pragma unroll
        for (int c = 0; c < 8; ++c) {
            float2 f = upk(acc[rp][c]);
            float y0 = lrelu(f.x + bias[c]);
            float y1 = lrelu(f.y + bias[c]);
            p00 += y0 * w30[c]; p01 += y0 * w31[c];
            p10 += y1 * w30[c]; p11 += y1 * w31[c];
        }
#pragma unroll
        for (int off = 8; off; off >>= 1) {
            p00 += __shfl_down_sync(0xffffffffu, p00, off, 16);
            p01 += __shfl_down_sync(0xffffffffu, p01, off, 16);
            p10 += __shfl_down_sync(0xffffffffu, p10, off, 16);
            p11 += __shfl_down_sync(0xffffffffu, p11, off, 16);
        }
        if (tc == 0) {
            int n = n0 + tr * 8 + rp * 2;
            *(float2*)(out + (size_t)(bt * NN + n) * 2)     = make_float2(p00 + bb0, p01 + bb1);
            *(float2*)(out + (size_t)(bt * NN + n + 1) * 2) = make_float2(p10 + bb0, p11 + bb1);
        }
    }
}

// ---------------- launch ----------------
extern "C" void kernel_launch(void* const* d_in, const int* in_sizes, int n_in,
                              void* d_out, int out_size) {
    const float* eb      = (const float*)d_in[0];
    const float* time_eb = (const float*)d_in[1];
    const float* node_eb = (const float*)d_in[2];
    const float* W1      = (const float*)d_in[3];
    const float* b1      = (const float*)d_in[4];
    const float* W3      = (const float*)d_in[5];
    const float* b3      = (const float*)d_in[6];
    const float* Pspa    = (const float*)d_in[7];
    const float* Bspa    = (const float*)d_in[8];
    const float* Ptem    = (const float*)d_in[9];
    const float* Btem    = (const float*)d_in[10];
    float* out = (float*)d_out;

    k_Q<<<EMB, 256>>>(W1, b1, Pspa, Bspa);
    k_Wc<<<32, 256>>>(node_eb);
    k_Wt<<<64, 256>>>(time_eb, Ptem);
    k_bias<<<NN + BT, 128>>>(node_eb, time_eb, Btem);
    k_spatial<<<dim3(6, NN), 256>>>(eb);
    k_temporal<<<dim3(4, BT), 256>>>(W3, b3, out);
}

// round 9
// speedup vs baseline: 1.1968x; 1.1968x over previous
#include <cuda_runtime.h>
#include <cuda_bf16.h>
#include <cstdint>

// Shapes (fixed)
#define BT   768
#define NN   512
#define DIN  64
#define HID  128
#define EMB  16

// ---------------- device-global scratch (no runtime allocs) ----------------
__device__ float g_QT[EMB * DIN * HID];     // QT[d][o*64+j] = (W1@Pspa[d])[j][o]
__device__ float g_CB[EMB * HID];
__device__ float g_PtemT[EMB * HID * HID];  // PtemT[d][o][i]
__device__ __nv_bfloat16 g_WcT_h[(size_t)NN * DIN * HID];   // [n][o][k]
__device__ __nv_bfloat16 g_WcT_l[(size_t)NN * DIN * HID];
__device__ __nv_bfloat16 g_WtT_h[(size_t)BT * HID * HID];   // [bt][o][i]
__device__ __nv_bfloat16 g_WtT_l[(size_t)BT * HID * HID];
__device__ float g_bspa[NN * HID];
__device__ float g_btem[BT * HID];
__device__ __nv_bfloat16 g_osp_h[(size_t)BT * NN * HID];    // [bt][n][o]
__device__ __nv_bfloat16 g_osp_l[(size_t)BT * NN * HID];

__device__ __forceinline__ float lrelu(float x) { return x >= 0.0f ? x : 0.01f * x; }

__device__ __forceinline__ uint32_t smem_to_u32(const void* p) {
    uint32_t a;
    asm("{ .reg .u64 t; cvta.to.shared.u64 t, %1; cvt.u32.u64 %0, t; }" : "=r"(a) : "l"(p));
    return a;
}
__device__ __forceinline__ void ldsm4(uint32_t& r0, uint32_t& r1, uint32_t& r2, uint32_t& r3,
                                      uint32_t a) {
    asm volatile("ldmatrix.sync.aligned.m8n8.x4.shared.b16 {%0,%1,%2,%3}, [%4];"
                 : "=r"(r0), "=r"(r1), "=r"(r2), "=r"(r3) : "r"(a));
}
__device__ __forceinline__ void mma16816(float* d, uint32_t a0, uint32_t a1, uint32_t a2,
                                         uint32_t a3, uint32_t b0, uint32_t b1) {
    asm volatile(
        "mma.sync.aligned.m16n8k16.row.col.f32.bf16.bf16.f32 "
        "{%0,%1,%2,%3}, {%4,%5,%6,%7}, {%8,%9}, {%0,%1,%2,%3};"
        : "+f"(d[0]), "+f"(d[1]), "+f"(d[2]), "+f"(d[3])
        : "r"(a0), "r"(a1), "r"(a2), "r"(a3), "r"(b0), "r"(b1));
}
__device__ __forceinline__ uint32_t packhl(float y0, float y1, uint32_t& lo) {
    __nv_bfloat16 h0 = __float2bfloat16(y0), h1 = __float2bfloat16(y1);
    lo = (uint32_t)__bfloat16_as_ushort(__float2bfloat16(y0 - __bfloat162float(h0))) |
         ((uint32_t)__bfloat16_as_ushort(__float2bfloat16(y1 - __bfloat162float(h1))) << 16);
    return (uint32_t)__bfloat16_as_ushort(h0) | ((uint32_t)__bfloat16_as_ushort(h1) << 16);
}

// ---------------- K0: QT[d] = (W1 @ Pspa[d])^T, CB[d] ----------------------
__global__ void k_Q(const float* __restrict__ W1, const float* __restrict__ b1,
                    const float* __restrict__ Pspa, const float* __restrict__ Bspa) {
    __shared__ float sW1[DIN * HID];
    int d = blockIdx.x, t = threadIdx.x;
    for (int l = t; l < DIN * HID; l += 256) sW1[l] = W1[l];
    __syncthreads();
    int o = t & 127, jh = t >> 7;
    const float* P = Pspa + d * HID * HID;
    float acc[32];
#pragma unroll
    for (int j = 0; j < 32; ++j) acc[j] = 0.f;
    for (int i = 0; i < HID; ++i) {
        float p = P[i * HID + o];
#pragma unroll
        for (int j = 0; j < 32; ++j) acc[j] += sW1[(jh * 32 + j) * HID + i] * p;
    }
#pragma unroll
    for (int j = 0; j < 32; ++j) g_QT[d * (DIN * HID) + o * DIN + jh * 32 + j] = acc[j];
    if (jh == 0) {
        float cb = Bspa[d * HID + o];
        for (int i = 0; i < HID; ++i) cb += b1[i] * P[i * HID + o];
        g_CB[d * HID + o] = cb;
    }
}

// ---------------- K0b: transpose Ptem per-d ---------------------------------
__global__ void k_tr(const float* __restrict__ Ptem) {
    __shared__ float s[32][33];
    int d = blockIdx.z;
    const float* src = Ptem + d * HID * HID;
    float* dst = g_PtemT + d * HID * HID;
    int x0 = blockIdx.x * 32, y0 = blockIdx.y * 32;
    int tx = threadIdx.x;
    for (int yy = threadIdx.y; yy < 32; yy += 8)
        s[yy][tx] = src[(y0 + yy) * HID + x0 + tx];
    __syncthreads();
    for (int yy = threadIdx.y; yy < 32; yy += 8)
        dst[(x0 + yy) * HID + y0 + tx] = s[tx][yy];
}

// ---------------- K1: WcT[n] (bf16 hi/lo) -----------------------------------
__global__ void k_Wc(const float* __restrict__ node_eb) {
    __shared__ float sQ[EMB][256];
    __shared__ float sNe[256 * EMB];
    int t = threadIdx.x;
    int base = blockIdx.x * 256;
    for (int l = t; l < EMB * 256; l += 256) {
        int d = l >> 8, e = l & 255;
        sQ[d][e] = g_QT[d * (DIN * HID) + base + e];
    }
    float q[EMB];
    __syncthreads();
#pragma unroll
    for (int d = 0; d < EMB; ++d) q[d] = sQ[d][t];
    for (int nc = 0; nc < 2; ++nc) {
        __syncthreads();
        for (int l = t; l < 256 * EMB; l += 256) sNe[l] = node_eb[nc * 256 * EMB + l];
        __syncthreads();
        for (int n = 0; n < 256; ++n) {
            float acc = 0.f;
#pragma unroll
            for (int d = 0; d < EMB; ++d) acc += sNe[n * EMB + d] * q[d];
            size_t idx = (size_t)(nc * 256 + n) * (DIN * HID) + base + t;
            __nv_bfloat16 h = __float2bfloat16(acc);
            g_WcT_h[idx] = h;
            g_WcT_l[idx] = __float2bfloat16(acc - __bfloat162float(h));
        }
    }
}

// ---------------- K2: WtT[bt] (bf16 hi/lo) ----------------------------------
__global__ void k_Wt(const float* __restrict__ time_eb) {
    __shared__ float sP[EMB][256];
    __shared__ float sTe[128 * EMB];
    int t = threadIdx.x;
    int base = blockIdx.x * 256;
    for (int l = t; l < EMB * 256; l += 256) {
        int d = l >> 8, e = l & 255;
        sP[d][e] = g_PtemT[d * (HID * HID) + base + e];
    }
    float q[EMB];
    __syncthreads();
#pragma unroll
    for (int d = 0; d < EMB; ++d) q[d] = sP[d][t];
    for (int c = 0; c < 6; ++c) {
        __syncthreads();
        for (int l = t; l < 128 * EMB; l += 256) sTe[l] = time_eb[c * 128 * EMB + l];
        __syncthreads();
        for (int r = 0; r < 128; ++r) {
            float acc = 0.f;
#pragma unroll
            for (int d = 0; d < EMB; ++d) acc += sTe[r * EMB + d] * q[d];
            size_t idx = (size_t)(c * 128 + r) * (HID * HID) + base + t;
            __nv_bfloat16 h = __float2bfloat16(acc);
            g_WtT_h[idx] = h;
            g_WtT_l[idx] = __float2bfloat16(acc - __bfloat162float(h));
        }
    }
}

// ---------------- K3: biases -------------------------------------------------
__global__ void k_bias(const float* __restrict__ node_eb, const float* __restrict__ time_eb,
                       const float* __restrict__ Btem) {
    int t = threadIdx.x, b = blockIdx.x;
    if (b < NN) {
        float acc = 0.f;
#pragma unroll
        for (int d = 0; d < EMB; ++d) acc += node_eb[b * EMB + d] * g_CB[d * HID + t];
        g_bspa[b * HID + t] = acc;
    } else {
        int bt = b - NN;
        float acc = 0.f;
#pragma unroll
        for (int d = 0; d < EMB; ++d) acc += time_eb[bt * EMB + d] * Btem[d * HID + t];
        g_btem[bt * HID + t] = acc;
    }
}

// ---------------- K4: spatial GEMM (mma.sync bf16, 3-pass hi/lo) -------------
// Tile: one n, 128 bt rows, 128 cols, K=64. 8 warps in 4(m)x2(n), warp 32x64.
#define SP_A   4096
#define SP_SMEM (4096 + 65536)

__global__ __launch_bounds__(256) void k_spatial(const float* __restrict__ eb) {
    extern __shared__ char sm[];
    uint32_t sb = smem_to_u32(sm);
    const uint32_t AH = SP_A, AL = SP_A + 16384, BHo = SP_A + 32768, BLo = SP_A + 49152;
    int t = threadIdx.x, lane = t & 31, wid = t >> 5;
    int n = blockIdx.y, bt0 = blockIdx.x * 128;
    if (t < 128) ((float*)sm)[t] = g_bspa[n * HID + t];

    // A stage: eb rows -> bf16 hi/lo, swizzled
    {
        int r = t >> 1, half = t & 1;
        const float* src = eb + ((size_t)(bt0 + r) * NN + n) * DIN + half * 32;
        unsigned xm = (unsigned)((r & 7) << 4);
        char* dh = sm + AH + r * 128;
        char* dl = sm + AL + r * 128;
#pragma unroll
        for (int g = 0; g < 4; ++g) {
            float4 v0 = *(const float4*)(src + g * 8);
            float4 v1 = *(const float4*)(src + g * 8 + 4);
            float xs[8] = {v0.x, v0.y, v0.z, v0.w, v1.x, v1.y, v1.z, v1.w};
            uint32_t hq[4], lq[4];
#pragma unroll
            for (int c = 0; c < 4; ++c) hq[c] = packhl(xs[2 * c], xs[2 * c + 1], lq[c]);
            unsigned kb = ((unsigned)((half * 32 + g * 8) * 2)) ^ xm;
            *(uint4*)(dh + kb) = *(uint4*)hq;
            *(uint4*)(dl + kb) = *(uint4*)lq;
        }
    }
    // B stage: WcT[n] hi/lo, swizzled
    {
        const uint4* Bhp = (const uint4*)(g_WcT_h + (size_t)n * (DIN * HID));
        const uint4* Blp = (const uint4*)(g_WcT_l + (size_t)n * (DIN * HID));
#pragma unroll
        for (int c = t; c < 1024; c += 256) {
            int row = c >> 3;
            unsigned off = (unsigned)(row * 128) + ((((unsigned)(c & 7)) * 16) ^ ((row & 7) << 4));
            *(uint4*)(sm + BHo + off) = Bhp[c];
            *(uint4*)(sm + BLo + off) = Blp[c];
        }
    }
    __syncthreads();

    float acc[2][8][4];
#pragma unroll
    for (int i = 0; i < 2; ++i)
#pragma unroll
        for (int j = 0; j < 8; ++j)
#pragma unroll
            for (int k = 0; k < 4; ++k) acc[i][j][k] = 0.f;

    int wm = wid & 3, wn = wid >> 2;
    uint32_t aB[2] = {sb + AH, sb + AL};
    uint32_t bB[2] = {sb + BHo, sb + BLo};
    const int PA[3] = {0, 0, 1}, PB[3] = {0, 1, 0};
    int arow = wm * 32 + (lane & 15);
    int brow = wn * 64 + (lane & 15);
    unsigned c16 = (unsigned)((lane >> 4) * 16);
#pragma unroll
    for (int p = 0; p < 3; ++p) {
        uint32_t ab = aB[PA[p]], bb = bB[PB[p]];
#pragma unroll
        for (int ks = 0; ks < 4; ++ks) {
            unsigned kb = (unsigned)(ks * 32);
            uint32_t af[2][4];
#pragma unroll
            for (int mf = 0; mf < 2; ++mf) {
                int row = arow + mf * 16;
                uint32_t addr = ab + row * 128 + ((kb + c16) ^ ((row & 7) << 4));
                ldsm4(af[mf][0], af[mf][1], af[mf][2], af[mf][3], addr);
            }
#pragma unroll
            for (int nq = 0; nq < 4; ++nq) {
                int row = brow + nq * 16;
                uint32_t addr = bb + row * 128 + ((kb + c16) ^ ((row & 7) << 4));
                uint32_t b0, b1, b2, b3;
                ldsm4(b0, b1, b2, b3, addr);
                mma16816(acc[0][nq * 2],     af[0][0], af[0][1], af[0][2], af[0][3], b0, b2);
                mma16816(acc[0][nq * 2 + 1], af[0][0], af[0][1], af[0][2], af[0][3], b1, b3);
                mma16816(acc[1][nq * 2],     af[1][0], af[1][1], af[1][2], af[1][3], b0, b2);
                mma16816(acc[1][nq * 2 + 1], af[1][0], af[1][1], af[1][2], af[1][3], b1, b3);
            }
        }
    }
    __syncthreads();
    // epilogue: bias+LReLU, hi/lo bf16 into smem (CH over A region, CL over B region)
    {
        int qr = lane >> 2, qc = lane & 3;
#pragma unroll
        for (int mf = 0; mf < 2; ++mf) {
#pragma unroll
            for (int nf = 0; nf < 8; ++nf) {
                int c0 = wn * 64 + nf * 8 + qc * 2;
                float bi0 = ((float*)sm)[c0], bi1 = ((float*)sm)[c0 + 1];
                int m0 = wm * 32 + mf * 16 + qr;
                uint32_t l0, l1;
                uint32_t h0 = packhl(lrelu(acc[mf][nf][0] + bi0), lrelu(acc[mf][nf][1] + bi1), l0);
                uint32_t h1 = packhl(lrelu(acc[mf][nf][2] + bi0), lrelu(acc[mf][nf][3] + bi1), l1);
                unsigned o0 = (unsigned)(m0 * 256) + (((unsigned)(c0 * 2)) ^ ((m0 & 7) << 5));
                int m1 = m0 + 8;
                unsigned o1 = (unsigned)(m1 * 256) + (((unsigned)(c0 * 2)) ^ ((m1 & 7) << 5));
                *(uint32_t*)(sm + AH + o0) = h0;
                *(uint32_t*)(sm + BHo + o0) = l0;
                *(uint32_t*)(sm + AH + o1) = h1;
                *(uint32_t*)(sm + BHo + o1) = l1;
            }
        }
    }
    __syncthreads();
    // coalesced copy to gmem (256B per row)
#pragma unroll
    for (int u = t; u < 2048; u += 256) {
        int row = u >> 4;
        unsigned o16 = (unsigned)((u & 15) * 16);
        unsigned off = (unsigned)(row * 256) + (o16 ^ ((row & 7) << 5));
        uint4 vh = *(uint4*)(sm + AH + off);
        uint4 vl = *(uint4*)(sm + BHo + off);
        size_t g = ((size_t)(bt0 + row) * NN + n) * HID + (u & 15) * 8;
        *(uint4*)(g_osp_h + g) = vh;
        *(uint4*)(g_osp_l + g) = vl;
    }
}

// ---------------- K5: temporal GEMM + LReLU + W3 projection ------------------
// Tile: one bt, 128 n rows, 128 cols, K=128 (2 chunks of 64).
#define TP_A   4096
#define TP_SMEM (4096 + 131072)

__global__ __launch_bounds__(256) void k_temporal(const float* __restrict__ W3,
                                                  const float* __restrict__ b3,
                                                  float* __restrict__ out) {
    extern __shared__ char sm[];
    uint32_t sb = smem_to_u32(sm);
    const uint32_t AH = TP_A, AL = TP_A + 32768, BHo = TP_A + 65536, BLo = TP_A + 98304;
    int t = threadIdx.x, lane = t & 31, wid = t >> 5;
    int bt = blockIdx.y, n0 = blockIdx.x * 128;
    if (t < 128) ((float*)sm)[t] = g_btem[bt * HID + t];
    if (t < 64) ((float4*)(sm + 512))[t] = ((const float4*)W3)[t];
    ((float*)(sm + 1536))[t] = 0.f;  // row sums [128][2]

    const uint4* Ahp = (const uint4*)(g_osp_h + ((size_t)bt * NN + n0) * HID);
    const uint4* Alp = (const uint4*)(g_osp_l + ((size_t)bt * NN + n0) * HID);
    const uint4* Bhp = (const uint4*)(g_WtT_h + (size_t)bt * (HID * HID));
    const uint4* Blp = (const uint4*)(g_WtT_l + (size_t)bt * (HID * HID));
#pragma unroll
    for (int c = t; c < 2048; c += 256) {
        int row = c >> 4, q = c & 15;
        unsigned off = (unsigned)((q >> 3) * 16384) + (unsigned)(row * 128) +
                       ((((unsigned)(q & 7)) * 16) ^ ((row & 7) << 4));
        *(uint4*)(sm + AH + off) = Ahp[c];
        *(uint4*)(sm + AL + off) = Alp[c];
        *(uint4*)(sm + BHo + off) = Bhp[c];
        *(uint4*)(sm + BLo + off) = Blp[c];
    }
    __syncthreads();

    float acc[2][8][4];
#pragma unroll
    for (int i = 0; i < 2; ++i)
#pragma unroll
        for (int j = 0; j < 8; ++j)
#pragma unroll
            for (int k = 0; k < 4; ++k) acc[i][j][k] = 0.f;

    int wm = wid & 3, wn = wid >> 2;
    uint32_t aB[2] = {sb + AH, sb + AL};
    uint32_t bB[2] = {sb + BHo, sb + BLo};
    const int PA[3] = {0, 0, 1}, PB[3] = {0, 1, 0};
    int arow = wm * 32 + (lane & 15);
    int brow = wn * 64 + (lane & 15);
    unsigned c16 = (unsigned)((lane >> 4) * 16);
#pragma unroll
    for (int p = 0; p < 3; ++p) {
#pragma unroll
        for (int ch = 0; ch < 2; ++ch) {
            uint32_t ab = aB[PA[p]] + ch * 16384, bb = bB[PB[p]] + ch * 16384;
#pragma unroll
            for (int ks = 0; ks < 4; ++ks) {
                unsigned kb = (unsigned)(ks * 32);
                uint32_t af[2][4];
#pragma unroll
                for (int mf = 0; mf < 2; ++mf) {
                    int row = arow + mf * 16;
                    uint32_t addr = ab + row * 128 + ((kb + c16) ^ ((row & 7) << 4));
                    ldsm4(af[mf][0], af[mf][1], af[mf][2], af[mf][3], addr);
                }
#pragma unroll
                for (int nq = 0; nq < 4; ++nq) {
                    int row = brow + nq * 16;
                    uint32_t addr = bb + row * 128 + ((kb + c16) ^ ((row & 7) << 4));
                    uint32_t b0, b1, b2, b3;
                    ldsm4(b0, b1, b2, b3, addr);
                    mma16816(acc[0][nq * 2],     af[0][0], af[0][1], af[0][2], af[0][3], b0, b2);
                    mma16816(acc[0][nq * 2 + 1], af[0][0], af[0][1], af[0][2], af[0][3], b1, b3);
                    mma16816(acc[1][nq * 2],     af[1][0], af[1][1], af[1][2], af[1][3], b0, b2);
                    mma16816(acc[1][nq * 2 + 1], af[1][0], af[1][1], af[1][2], af[1][3], b1, b3);
                }
            }
        }
    }
    __syncthreads();
    // epilogue: bias+LReLU, project to 2 outputs, reduce across cols
    {
        int qr = lane >> 2, qc = lane & 3;
        const float* bias = (const float*)sm;
        const float* w3s = (const float*)(sm + 512);
        float s0[4] = {0.f, 0.f, 0.f, 0.f}, s1[4] = {0.f, 0.f, 0.f, 0.f};
#pragma unroll
        for (int mf = 0; mf < 2; ++mf) {
#pragma unroll
            for (int nf = 0; nf < 8; ++nf) {
                int c0 = wn * 64 + nf * 8 + qc * 2;
                float bi0 = bias[c0], bi1 = bias[c0 + 1];
                float w00 = w3s[c0 * 2], w01 = w3s[c0 * 2 + 1];
                float w10 = w3s[c0 * 2 + 2], w11 = w3s[c0 * 2 + 3];
                float y00 = lrelu(acc[mf][nf][0] + bi0);
                float y01 = lrelu(acc[mf][nf][1] + bi1);
                float y10 = lrelu(acc[mf][nf][2] + bi0);
                float y11 = lrelu(acc[mf][nf][3] + bi1);
                s0[mf * 2 + 0] += y00 * w00 + y01 * w10;
                s1[mf * 2 + 0] += y00 * w01 + y01 * w11;
                s0[mf * 2 + 1] += y10 * w00 + y11 * w10;
                s1[mf * 2 + 1] += y10 * w01 + y11 * w11;
            }
        }
        float* sums = (float*)(sm + 1536);
#pragma unroll
        for (int i = 0; i < 4; ++i) {
            float v0 = s0[i], v1 = s1[i];
            v0 += __shfl_xor_sync(0xffffffffu, v0, 1);
            v0 += __shfl_xor_sync(0xffffffffu, v0, 2);
            v1 += __shfl_xor_sync(0xffffffffu, v1, 1);
            v1 += __shfl_xor_sync(0xffffffffu, v1, 2);
            if (qc == 0) {
                int row = wm * 32 + (i >> 1) * 16 + qr + (i & 1) * 8;
                atomicAdd(sums + row * 2, v0);
                atomicAdd(sums + row * 2 + 1, v1);
            }
        }
    }
    __syncthreads();
    if (t < 128) {
        const float* sums = (const float*)(sm + 1536);
        float2 o;
        o.x = sums[t * 2] + __ldg(b3);
        o.y = sums[t * 2 + 1] + __ldg(b3 + 1);
        *(float2*)(out + ((size_t)bt * NN + n0 + t) * 2) = o;
    }
}

// ---------------- launch ----------------
extern "C" void kernel_launch(void* const* d_in, const int* in_sizes, int n_in,
                              void* d_out, int out_size) {
    const float* eb      = (const float*)d_in[0];
    const float* time_eb = (const float*)d_in[1];
    const float* node_eb = (const float*)d_in[2];
    const float* W1      = (const float*)d_in[3];
    const float* b1      = (const float*)d_in[4];
    const float* W3      = (const float*)d_in[5];
    const float* b3      = (const float*)d_in[6];
    const float* Pspa    = (const float*)d_in[7];
    const float* Bspa    = (const float*)d_in[8];
    const float* Ptem    = (const float*)d_in[9];
    const float* Btem    = (const float*)d_in[10];
    float* out = (float*)d_out;

    cudaFuncSetAttribute(k_spatial, cudaFuncAttributeMaxDynamicSharedMemorySize, SP_SMEM);
    cudaFuncSetAttribute(k_temporal, cudaFuncAttributeMaxDynamicSharedMemorySize, TP_SMEM);

    k_Q<<<EMB, 256>>>(W1, b1, Pspa, Bspa);
    k_tr<<<dim3(4, 4, EMB), dim3(32, 8)>>>(Ptem);
    k_Wc<<<32, 256>>>(node_eb);
    k_Wt<<<64, 256>>>(time_eb);
    k_bias<<<NN + BT, 128>>>(node_eb, time_eb, Btem);
    k_spatial<<<dim3(6, NN), 256, SP_SMEM>>>(eb);
    k_temporal<<<dim3(4, BT), 256, TP_SMEM>>>(W3, b3, out);
}

// round 10
// speedup vs baseline: 1.5047x; 1.2573x over previous
#include <cuda_runtime.h>
#include <cuda_bf16.h>
#include <cstdint>

// Shapes (fixed)
#define BT   768
#define NN   512
#define DIN  64
#define HID  128
#define EMB  16

// ---------------- device-global scratch (no runtime allocs) ----------------
__device__ float g_QT[EMB * DIN * HID];     // QT[d][o*64+j] = (W1@Pspa[d])[j][o]
__device__ float g_CB[EMB * HID];
__device__ float g_PtemT[EMB * HID * HID];  // PtemT[d][o][i]
__device__ __nv_bfloat16 g_WcT_h[(size_t)NN * DIN * HID];   // [n][o][k]
__device__ __nv_bfloat16 g_WcT_l[(size_t)NN * DIN * HID];
__device__ __nv_bfloat16 g_WtT_h[(size_t)BT * HID * HID];   // [bt][o][i]
__device__ __nv_bfloat16 g_WtT_l[(size_t)BT * HID * HID];
__device__ float g_bspa[NN * HID];
__device__ float g_btem[BT * HID];
__device__ __nv_bfloat16 g_osp_h[(size_t)BT * NN * HID];    // [bt][n][o]
__device__ __nv_bfloat16 g_osp_l[(size_t)BT * NN * HID];

__device__ __forceinline__ float lrelu(float x) { return x >= 0.0f ? x : 0.01f * x; }

__device__ __forceinline__ uint32_t smem_to_u32(const void* p) {
    uint32_t a;
    asm("{ .reg .u64 t; cvta.to.shared.u64 t, %1; cvt.u32.u64 %0, t; }" : "=r"(a) : "l"(p));
    return a;
}
__device__ __forceinline__ void ldsm4(uint32_t& r0, uint32_t& r1, uint32_t& r2, uint32_t& r3,
                                      uint32_t a) {
    asm volatile("ldmatrix.sync.aligned.m8n8.x4.shared.b16 {%0,%1,%2,%3}, [%4];"
                 : "=r"(r0), "=r"(r1), "=r"(r2), "=r"(r3) : "r"(a));
}
__device__ __forceinline__ void mma16816(float* d, uint32_t a0, uint32_t a1, uint32_t a2,
                                         uint32_t a3, uint32_t b0, uint32_t b1) {
    asm volatile(
        "mma.sync.aligned.m16n8k16.row.col.f32.bf16.bf16.f32 "
        "{%0,%1,%2,%3}, {%4,%5,%6,%7}, {%8,%9}, {%0,%1,%2,%3};"
        : "+f"(d[0]), "+f"(d[1]), "+f"(d[2]), "+f"(d[3])
        : "r"(a0), "r"(a1), "r"(a2), "r"(a3), "r"(b0), "r"(b1));
}
__device__ __forceinline__ uint32_t packhl(float y0, float y1, uint32_t& lo) {
    __nv_bfloat16 h0 = __float2bfloat16(y0), h1 = __float2bfloat16(y1);
    lo = (uint32_t)__bfloat16_as_ushort(__float2bfloat16(y0 - __bfloat162float(h0))) |
         ((uint32_t)__bfloat16_as_ushort(__float2bfloat16(y1 - __bfloat162float(h1))) << 16);
    return (uint32_t)__bfloat16_as_ushort(h0) | ((uint32_t)__bfloat16_as_ushort(h1) << 16);
}

// cp.async helpers (Ampere+ PTX, valid on compute_103)
#define CP16(dst, src) \
    asm volatile("cp.async.cg.shared.global [%0], [%1], 16;" \
                 :: "r"((uint32_t)(dst)), "l"((const void*)(src)) : "memory")
#define CP_COMMIT() asm volatile("cp.async.commit_group;" ::: "memory")
#define CP_WAIT(n)  asm volatile("cp.async.wait_group %0;" :: "n"(n) : "memory")

// ---------------- K0: QT[d] = (W1 @ Pspa[d])^T, CB[d] -----------------------
// grid (EMB, 4): block = (d, 32-o chunk). 256 thr = 32 o x 8 j-groups.
__global__ __launch_bounds__(256) void k_Q(const float* __restrict__ W1,
                                           const float* __restrict__ b1,
                                           const float* __restrict__ Pspa,
                                           const float* __restrict__ Bspa) {
    __shared__ float sW1[DIN * HID];
    __shared__ float sb1[HID];
    int t = threadIdx.x;
    for (int l = t; l < DIN * HID; l += 256) sW1[l] = W1[l];
    if (t < HID) sb1[t] = b1[t];
    __syncthreads();
    int d = blockIdx.x, oc = blockIdx.y;
    int o = oc * 32 + (t & 31), jg = t >> 5;
    const float* P = Pspa + d * HID * HID;
    float acc[8];
#pragma unroll
    for (int j = 0; j < 8; ++j) acc[j] = 0.f;
    float cb = 0.f;
    for (int i = 0; i < HID; ++i) {
        float p = P[i * HID + o];
#pragma unroll
        for (int j = 0; j < 8; ++j) acc[j] += sW1[(jg * 8 + j) * HID + i] * p;
        if (jg == 0) cb += sb1[i] * p;
    }
    float* q = g_QT + d * (DIN * HID) + o * DIN + jg * 8;
    *(float4*)q = make_float4(acc[0], acc[1], acc[2], acc[3]);
    *(float4*)(q + 4) = make_float4(acc[4], acc[5], acc[6], acc[7]);
    if (jg == 0) g_CB[d * HID + o] = cb + Bspa[d * HID + o];
}

// ---------------- K0b: transpose Ptem per-d ---------------------------------
__global__ void k_tr(const float* __restrict__ Ptem) {
    __shared__ float s[32][33];
    int d = blockIdx.z;
    const float* src = Ptem + d * HID * HID;
    float* dst = g_PtemT + d * HID * HID;
    int x0 = blockIdx.x * 32, y0 = blockIdx.y * 32;
    int tx = threadIdx.x;
    for (int yy = threadIdx.y; yy < 32; yy += 8)
        s[yy][tx] = src[(y0 + yy) * HID + x0 + tx];
    __syncthreads();
    for (int yy = threadIdx.y; yy < 32; yy += 8)
        dst[(x0 + yy) * HID + y0 + tx] = s[tx][yy];
}

// ---------------- K1: WcT (bf16 hi/lo). grid (32 n-groups, 4 chunks) --------
// Each block: 16 n x 2048 elems. Thread: 2 float4 positions, 16 d, 16 n.
__global__ __launch_bounds__(256) void k_Wc(const float* __restrict__ node_eb) {
    __shared__ float sNe[256];  // [n(16)][d(16)]
    int t = threadIdx.x;
    int nb = blockIdx.x, chunk = blockIdx.y;
    sNe[t] = node_eb[(nb * 16 + (t >> 4)) * EMB + (t & 15)];
    __syncthreads();
    const float4* Q4 = (const float4*)g_QT;
#pragma unroll
    for (int it = 0; it < 2; ++it) {
        int p4 = chunk * 512 + it * 256 + t;
        float4 vq[EMB];
#pragma unroll
        for (int d = 0; d < EMB; ++d) vq[d] = Q4[d * 2048 + p4];
#pragma unroll
        for (int n = 0; n < 16; ++n) {
            float4 a = make_float4(0.f, 0.f, 0.f, 0.f);
#pragma unroll
            for (int d = 0; d < EMB; ++d) {
                float c = sNe[n * 16 + d];
                a.x += c * vq[d].x; a.y += c * vq[d].y;
                a.z += c * vq[d].z; a.w += c * vq[d].w;
            }
            uint32_t l0, l1;
            uint32_t h0 = packhl(a.x, a.y, l0);
            uint32_t h1 = packhl(a.z, a.w, l1);
            size_t row = (size_t)(nb * 16 + n);
            ((uint2*)g_WcT_h)[row * 2048 + p4] = make_uint2(h0, h1);
            ((uint2*)g_WcT_l)[row * 2048 + p4] = make_uint2(l0, l1);
        }
    }
}

// ---------------- K2: WtT (bf16 hi/lo). grid (48 bt-groups, 4 chunks) -------
__global__ __launch_bounds__(256) void k_Wt(const float* __restrict__ time_eb) {
    __shared__ float sTe[256];  // [bt(16)][d(16)]
    int t = threadIdx.x;
    int nb = blockIdx.x, chunk = blockIdx.y;
    sTe[t] = time_eb[(nb * 16 + (t >> 4)) * EMB + (t & 15)];
    __syncthreads();
    const float4* P4 = (const float4*)g_PtemT;
#pragma unroll
    for (int it = 0; it < 4; ++it) {
        int p4 = chunk * 1024 + it * 256 + t;
        float4 vq[EMB];
#pragma unroll
        for (int d = 0; d < EMB; ++d) vq[d] = P4[d * 4096 + p4];
#pragma unroll
        for (int n = 0; n < 16; ++n) {
            float4 a = make_float4(0.f, 0.f, 0.f, 0.f);
#pragma unroll
            for (int d = 0; d < EMB; ++d) {
                float c = sTe[n * 16 + d];
                a.x += c * vq[d].x; a.y += c * vq[d].y;
                a.z += c * vq[d].z; a.w += c * vq[d].w;
            }
            uint32_t l0, l1;
            uint32_t h0 = packhl(a.x, a.y, l0);
            uint32_t h1 = packhl(a.z, a.w, l1);
            size_t row = (size_t)(nb * 16 + n);
            ((uint2*)g_WtT_h)[row * 4096 + p4] = make_uint2(h0, h1);
            ((uint2*)g_WtT_l)[row * 4096 + p4] = make_uint2(l0, l1);
        }
    }
}

// ---------------- K3: biases -------------------------------------------------
__global__ void k_bias(const float* __restrict__ node_eb, const float* __restrict__ time_eb,
                       const float* __restrict__ Btem) {
    int t = threadIdx.x, b = blockIdx.x;
    if (b < NN) {
        float acc = 0.f;
#pragma unroll
        for (int d = 0; d < EMB; ++d) acc += node_eb[b * EMB + d] * g_CB[d * HID + t];
        g_bspa[b * HID + t] = acc;
    } else {
        int bt = b - NN;
        float acc = 0.f;
#pragma unroll
        for (int d = 0; d < EMB; ++d) acc += time_eb[bt * EMB + d] * Btem[d * HID + t];
        g_btem[bt * HID + t] = acc;
    }
}

// ---------------- K4: spatial GEMM (mma.sync bf16, 3-pass hi/lo) -------------
#define SP_A   4096
#define SP_SMEM (4096 + 65536)

__global__ __launch_bounds__(256) void k_spatial(const float* __restrict__ eb) {
    extern __shared__ char sm[];
    uint32_t sb = smem_to_u32(sm);
    const uint32_t AH = SP_A, AL = SP_A + 16384, BHo = SP_A + 32768, BLo = SP_A + 49152;
    int t = threadIdx.x, lane = t & 31, wid = t >> 5;
    int n = blockIdx.y, bt0 = blockIdx.x * 128;

    // B stage via cp.async FIRST (overlaps with A conversion below)
    {
        const uint4* Bhp = (const uint4*)(g_WcT_h + (size_t)n * (DIN * HID));
        const uint4* Blp = (const uint4*)(g_WcT_l + (size_t)n * (DIN * HID));
#pragma unroll
        for (int c = t; c < 1024; c += 256) {
            int row = c >> 3;
            unsigned off = (unsigned)(row * 128) + ((((unsigned)(c & 7)) * 16) ^ ((row & 7) << 4));
            CP16(sb + BHo + off, Bhp + c);
            CP16(sb + BLo + off, Blp + c);
        }
        CP_COMMIT();
    }
    if (t < 128) ((float*)sm)[t] = g_bspa[n * HID + t];

    // A stage: eb rows -> bf16 hi/lo, swizzled (arithmetic overlaps B cp.async)
    {
        int r = t >> 1, half = t & 1;
        const float* src = eb + ((size_t)(bt0 + r) * NN + n) * DIN + half * 32;
        unsigned xm = (unsigned)((r & 7) << 4);
        char* dh = sm + AH + r * 128;
        char* dl = sm + AL + r * 128;
#pragma unroll
        for (int g = 0; g < 4; ++g) {
            float4 v0 = *(const float4*)(src + g * 8);
            float4 v1 = *(const float4*)(src + g * 8 + 4);
            float xs[8] = {v0.x, v0.y, v0.z, v0.w, v1.x, v1.y, v1.z, v1.w};
            uint32_t hq[4], lq[4];
#pragma unroll
            for (int c = 0; c < 4; ++c) hq[c] = packhl(xs[2 * c], xs[2 * c + 1], lq[c]);
            unsigned kb = ((unsigned)((half * 32 + g * 8) * 2)) ^ xm;
            *(uint4*)(dh + kb) = *(uint4*)hq;
            *(uint4*)(dl + kb) = *(uint4*)lq;
        }
    }
    CP_WAIT(0);
    __syncthreads();

    float acc[2][8][4];
#pragma unroll
    for (int i = 0; i < 2; ++i)
#pragma unroll
        for (int j = 0; j < 8; ++j)
#pragma unroll
            for (int k = 0; k < 4; ++k) acc[i][j][k] = 0.f;

    int wm = wid & 3, wn = wid >> 2;
    uint32_t aB[2] = {sb + AH, sb + AL};
    uint32_t bB[2] = {sb + BHo, sb + BLo};
    const int PA[3] = {0, 0, 1}, PB[3] = {0, 1, 0};
    int arow = wm * 32 + (lane & 15);
    int brow = wn * 64 + (lane & 15);
    unsigned c16 = (unsigned)((lane >> 4) * 16);
#pragma unroll
    for (int p = 0; p < 3; ++p) {
        uint32_t ab = aB[PA[p]], bb = bB[PB[p]];
#pragma unroll
        for (int ks = 0; ks < 4; ++ks) {
            unsigned kb = (unsigned)(ks * 32);
            uint32_t af[2][4];
#pragma unroll
            for (int mf = 0; mf < 2; ++mf) {
                int row = arow + mf * 16;
                uint32_t addr = ab + row * 128 + ((kb + c16) ^ ((row & 7) << 4));
                ldsm4(af[mf][0], af[mf][1], af[mf][2], af[mf][3], addr);
            }
#pragma unroll
            for (int nq = 0; nq < 4; ++nq) {
                int row = brow + nq * 16;
                uint32_t addr = bb + row * 128 + ((kb + c16) ^ ((row & 7) << 4));
                uint32_t b0, b1, b2, b3;
                ldsm4(b0, b1, b2, b3, addr);
                mma16816(acc[0][nq * 2],     af[0][0], af[0][1], af[0][2], af[0][3], b0, b2);
                mma16816(acc[0][nq * 2 + 1], af[0][0], af[0][1], af[0][2], af[0][3], b1, b3);
                mma16816(acc[1][nq * 2],     af[1][0], af[1][1], af[1][2], af[1][3], b0, b2);
                mma16816(acc[1][nq * 2 + 1], af[1][0], af[1][1], af[1][2], af[1][3], b1, b3);
            }
        }
    }
    __syncthreads();
    // epilogue: bias+LReLU, hi/lo bf16 into smem
    {
        int qr = lane >> 2, qc = lane & 3;
#pragma unroll
        for (int mf = 0; mf < 2; ++mf) {
#pragma unroll
            for (int nf = 0; nf < 8; ++nf) {
                int c0 = wn * 64 + nf * 8 + qc * 2;
                float bi0 = ((float*)sm)[c0], bi1 = ((float*)sm)[c0 + 1];
                int m0 = wm * 32 + mf * 16 + qr;
                uint32_t l0, l1;
                uint32_t h0 = packhl(lrelu(acc[mf][nf][0] + bi0), lrelu(acc[mf][nf][1] + bi1), l0);
                uint32_t h1 = packhl(lrelu(acc[mf][nf][2] + bi0), lrelu(acc[mf][nf][3] + bi1), l1);
                unsigned o0 = (unsigned)(m0 * 256) + (((unsigned)(c0 * 2)) ^ ((m0 & 7) << 5));
                int m1 = m0 + 8;
                unsigned o1 = (unsigned)(m1 * 256) + (((unsigned)(c0 * 2)) ^ ((m1 & 7) << 5));
                *(uint32_t*)(sm + AH + o0) = h0;
                *(uint32_t*)(sm + BHo + o0) = l0;
                *(uint32_t*)(sm + AH + o1) = h1;
                *(uint32_t*)(sm + BHo + o1) = l1;
            }
        }
    }
    __syncthreads();
#pragma unroll
    for (int u = t; u < 2048; u += 256) {
        int row = u >> 4;
        unsigned o16 = (unsigned)((u & 15) * 16);
        unsigned off = (unsigned)(row * 256) + (o16 ^ ((row & 7) << 5));
        uint4 vh = *(uint4*)(sm + AH + off);
        uint4 vl = *(uint4*)(sm + BHo + off);
        size_t g = ((size_t)(bt0 + row) * NN + n) * HID + (u & 15) * 8;
        *(uint4*)(g_osp_h + g) = vh;
        *(uint4*)(g_osp_l + g) = vl;
    }
}

// ---------------- K5: temporal GEMM + LReLU + W3 projection ------------------
// cp.async 2-stage pipeline over the two K=64 chunks.
#define TP_A   4096
#define TP_SMEM (4096 + 131072)

__global__ __launch_bounds__(256) void k_temporal(const float* __restrict__ W3,
                                                  const float* __restrict__ b3,
                                                  float* __restrict__ out) {
    extern __shared__ char sm[];
    uint32_t sb = smem_to_u32(sm);
    const uint32_t AH = TP_A, AL = TP_A + 32768, BHo = TP_A + 65536, BLo = TP_A + 98304;
    int t = threadIdx.x, lane = t & 31, wid = t >> 5;
    int bt = blockIdx.y, n0 = blockIdx.x * 128;

    const uint4* Ahp = (const uint4*)(g_osp_h + ((size_t)bt * NN + n0) * HID);
    const uint4* Alp = (const uint4*)(g_osp_l + ((size_t)bt * NN + n0) * HID);
    const uint4* Bhp = (const uint4*)(g_WtT_h + (size_t)bt * (HID * HID));
    const uint4* Blp = (const uint4*)(g_WtT_l + (size_t)bt * (HID * HID));
    // issue both chunk groups up front (ch0 group, then ch1 group)
#pragma unroll
    for (int ch = 0; ch < 2; ++ch) {
#pragma unroll
        for (int u = t; u < 1024; u += 256) {
            int row = u >> 3, q8 = u & 7;
            int c = row * 16 + ch * 8 + q8;
            unsigned off = (unsigned)(ch * 16384) + (unsigned)(row * 128) +
                           ((((unsigned)q8) * 16) ^ ((row & 7) << 4));
            CP16(sb + AH + off, Ahp + c);
            CP16(sb + AL + off, Alp + c);
            CP16(sb + BHo + off, Bhp + c);
            CP16(sb + BLo + off, Blp + c);
        }
        CP_COMMIT();
    }
    if (t < 128) ((float*)sm)[t] = g_btem[bt * HID + t];
    if (t < 64) ((float4*)(sm + 512))[t] = ((const float4*)W3)[t];
    ((float*)(sm + 1536))[t] = 0.f;  // row sums [128][2]

    float acc[2][8][4];
#pragma unroll
    for (int i = 0; i < 2; ++i)
#pragma unroll
        for (int j = 0; j < 8; ++j)
#pragma unroll
            for (int k = 0; k < 4; ++k) acc[i][j][k] = 0.f;

    int wm = wid & 3, wn = wid >> 2;
    uint32_t aB[2] = {sb + AH, sb + AL};
    uint32_t bB[2] = {sb + BHo, sb + BLo};
    const int PA[3] = {0, 0, 1}, PB[3] = {0, 1, 0};
    int arow = wm * 32 + (lane & 15);
    int brow = wn * 64 + (lane & 15);
    unsigned c16 = (unsigned)((lane >> 4) * 16);

#pragma unroll
    for (int ch = 0; ch < 2; ++ch) {
        if (ch == 0) { CP_WAIT(1); } else { CP_WAIT(0); }
        __syncthreads();
#pragma unroll
        for (int p = 0; p < 3; ++p) {
            uint32_t ab = aB[PA[p]] + ch * 16384, bb = bB[PB[p]] + ch * 16384;
#pragma unroll
            for (int ks = 0; ks < 4; ++ks) {
                unsigned kb = (unsigned)(ks * 32);
                uint32_t af[2][4];
#pragma unroll
                for (int mf = 0; mf < 2; ++mf) {
                    int row = arow + mf * 16;
                    uint32_t addr = ab + row * 128 + ((kb + c16) ^ ((row & 7) << 4));
                    ldsm4(af[mf][0], af[mf][1], af[mf][2], af[mf][3], addr);
                }
#pragma unroll
                for (int nq = 0; nq < 4; ++nq) {
                    int row = brow + nq * 16;
                    uint32_t addr = bb + row * 128 + ((kb + c16) ^ ((row & 7) << 4));
                    uint32_t b0, b1, b2, b3;
                    ldsm4(b0, b1, b2, b3, addr);
                    mma16816(acc[0][nq * 2],     af[0][0], af[0][1], af[0][2], af[0][3], b0, b2);
                    mma16816(acc[0][nq * 2 + 1], af[0][0], af[0][1], af[0][2], af[0][3], b1, b3);
                    mma16816(acc[1][nq * 2],     af[1][0], af[1][1], af[1][2], af[1][3], b0, b2);
                    mma16816(acc[1][nq * 2 + 1], af[1][0], af[1][1], af[1][2], af[1][3], b1, b3);
                }
            }
        }
    }
    __syncthreads();
    // epilogue: bias+LReLU, project to 2 outputs, reduce across cols
    {
        int qr = lane >> 2, qc = lane & 3;
        const float* bias = (const float*)sm;
        const float* w3s = (const float*)(sm + 512);
        float s0[4] = {0.f, 0.f, 0.f, 0.f}, s1[4] = {0.f, 0.f, 0.f, 0.f};
#pragma unroll
        for (int mf = 0; mf < 2; ++mf) {
#pragma unroll
            for (int nf = 0; nf < 8; ++nf) {
                int c0 = wn * 64 + nf * 8 + qc * 2;
                float bi0 = bias[c0], bi1 = bias[c0 + 1];
                float w00 = w3s[c0 * 2], w01 = w3s[c0 * 2 + 1];
                float w10 = w3s[c0 * 2 + 2], w11 = w3s[c0 * 2 + 3];
                float y00 = lrelu(acc[mf][nf][0] + bi0);
                float y01 = lrelu(acc[mf][nf][1] + bi1);
                float y10 = lrelu(acc[mf][nf][2] + bi0);
                float y11 = lrelu(acc[mf][nf][3] + bi1);
                s0[mf * 2 + 0] += y00 * w00 + y01 * w10;
                s1[mf * 2 + 0] += y00 * w01 + y01 * w11;
                s0[mf * 2 + 1] += y10 * w00 + y11 * w10;
                s1[mf * 2 + 1] += y10 * w01 + y11 * w11;
            }
        }
        float* sums = (float*)(sm + 1536);
#pragma unroll
        for (int i = 0; i < 4; ++i) {
            float v0 = s0[i], v1 = s1[i];
            v0 += __shfl_xor_sync(0xffffffffu, v0, 1);
            v0 += __shfl_xor_sync(0xffffffffu, v0, 2);
            v1 += __shfl_xor_sync(0xffffffffu, v1, 1);
            v1 += __shfl_xor_sync(0xffffffffu, v1, 2);
            if (qc == 0) {
                int row = wm * 32 + (i >> 1) * 16 + qr + (i & 1) * 8;
                atomicAdd(sums + row * 2, v0);
                atomicAdd(sums + row * 2 + 1, v1);
            }
        }
    }
    __syncthreads();
    if (t < 128) {
        const float* sums = (const float*)(sm + 1536);
        float2 o;
        o.x = sums[t * 2] + __ldg(b3);
        o.y = sums[t * 2 + 1] + __ldg(b3 + 1);
        *(float2*)(out + ((size_t)bt * NN + n0 + t) * 2) = o;
    }
}

// ---------------- launch ----------------
extern "C" void kernel_launch(void* const* d_in, const int* in_sizes, int n_in,
                              void* d_out, int out_size) {
    const float* eb      = (const float*)d_in[0];
    const float* time_eb = (const float*)d_in[1];
    const float* node_eb = (const float*)d_in[2];
    const float* W1      = (const float*)d_in[3];
    const float* b1      = (const float*)d_in[4];
    const float* W3      = (const float*)d_in[5];
    const float* b3      = (const float*)d_in[6];
    const float* Pspa    = (const float*)d_in[7];
    const float* Bspa    = (const float*)d_in[8];
    const float* Ptem    = (const float*)d_in[9];
    const float* Btem    = (const float*)d_in[10];
    float* out = (float*)d_out;

    cudaFuncSetAttribute(k_spatial, cudaFuncAttributeMaxDynamicSharedMemorySize, SP_SMEM);
    cudaFuncSetAttribute(k_temporal, cudaFuncAttributeMaxDynamicSharedMemorySize, TP_SMEM);

    k_Q<<<dim3(EMB, 4), 256>>>(W1, b1, Pspa, Bspa);
    k_tr<<<dim3(4, 4, EMB), dim3(32, 8)>>>(Ptem);
    k_Wc<<<dim3(32, 4), 256>>>(node_eb);
    k_Wt<<<dim3(48, 4), 256>>>(time_eb);
    k_bias<<<NN + BT, 128>>>(node_eb, time_eb, Btem);
    k_spatial<<<dim3(6, NN), 256, SP_SMEM>>>(eb);
    k_temporal<<<dim3(4, BT), 256, TP_SMEM>>>(W3, b3, out);
}

// round 14
// speedup vs baseline: 1.5050x; 1.0002x over previous
#include <cuda_runtime.h>
#include <cuda_bf16.h>
#include <cstdint>

// Shapes (fixed)
#define BT   768
#define NN   512
#define DIN  64
#define HID  128
#define EMB  16

// ---------------- device-global scratch (no runtime allocs) ----------------
__device__ float g_QT[EMB * DIN * HID];     // QT[d][o*64+j] = (W1@Pspa[d])[j][o]
__device__ float g_CB[EMB * HID];
__device__ float g_PtemT[EMB * HID * HID];  // PtemT[d][o][i]
__device__ __nv_bfloat16 g_WcT_h[(size_t)NN * DIN * HID];   // [n][o][k]
__device__ __nv_bfloat16 g_WcT_l[(size_t)NN * DIN * HID];
__device__ __nv_bfloat16 g_WtT_h[(size_t)BT * HID * HID];   // [bt][o][i]
__device__ __nv_bfloat16 g_WtT_l[(size_t)BT * HID * HID];
__device__ float g_bspa[NN * HID];
__device__ float g_btem[BT * HID];
__device__ __nv_bfloat16 g_osp_h[(size_t)BT * NN * HID];    // [bt][n][o]
__device__ __nv_bfloat16 g_osp_l[(size_t)BT * NN * HID];

__device__ __forceinline__ float lrelu(float x) { return x >= 0.0f ? x : 0.01f * x; }

__device__ __forceinline__ uint32_t smem_to_u32(const void* p) {
    uint32_t a;
    asm("{ .reg .u64 t; cvta.to.shared.u64 t, %1; cvt.u32.u64 %0, t; }" : "=r"(a) : "l"(p));
    return a;
}
__device__ __forceinline__ void ldsm4(uint32_t& r0, uint32_t& r1, uint32_t& r2, uint32_t& r3,
                                      uint32_t a) {
    asm volatile("ldmatrix.sync.aligned.m8n8.x4.shared.b16 {%0,%1,%2,%3}, [%4];"
                 : "=r"(r0), "=r"(r1), "=r"(r2), "=r"(r3) : "r"(a));
}
__device__ __forceinline__ void mma16816(float* d, uint32_t a0, uint32_t a1, uint32_t a2,
                                         uint32_t a3, uint32_t b0, uint32_t b1) {
    asm volatile(
        "mma.sync.aligned.m16n8k16.row.col.f32.bf16.bf16.f32 "
        "{%0,%1,%2,%3}, {%4,%5,%6,%7}, {%8,%9}, {%0,%1,%2,%3};"
        : "+f"(d[0]), "+f"(d[1]), "+f"(d[2]), "+f"(d[3])
        : "r"(a0), "r"(a1), "r"(a2), "r"(a3), "r"(b0), "r"(b1));
}
__device__ __forceinline__ uint32_t packhl(float y0, float y1, uint32_t& lo) {
    __nv_bfloat16 h0 = __float2bfloat16(y0), h1 = __float2bfloat16(y1);
    lo = (uint32_t)__bfloat16_as_ushort(__float2bfloat16(y0 - __bfloat162float(h0))) |
         ((uint32_t)__bfloat16_as_ushort(__float2bfloat16(y1 - __bfloat162float(h1))) << 16);
    return (uint32_t)__bfloat16_as_ushort(h0) | ((uint32_t)__bfloat16_as_ushort(h1) << 16);
}

// cp.async helpers
#define CP16(dst, src) \
    asm volatile("cp.async.cg.shared.global [%0], [%1], 16;" \
                 :: "r"((uint32_t)(dst)), "l"((const void*)(src)) : "memory")
#define CP_COMMIT() asm volatile("cp.async.commit_group;" ::: "memory")
#define CP_WAIT(n)  asm volatile("cp.async.wait_group %0;" :: "n"(n) : "memory")

// ---------------- K0: QT[d] = (W1 @ Pspa[d])^T, CB[d] -----------------------
__global__ __launch_bounds__(256) void k_Q(const float* __restrict__ W1,
                                           const float* __restrict__ b1,
                                           const float* __restrict__ Pspa,
                                           const float* __restrict__ Bspa) {
    __shared__ float sW1[DIN * HID];
    __shared__ float sb1[HID];
    int t = threadIdx.x;
    for (int l = t; l < DIN * HID; l += 256) sW1[l] = W1[l];
    if (t < HID) sb1[t] = b1[t];
    __syncthreads();
    int d = blockIdx.x, oc = blockIdx.y;
    int o = oc * 32 + (t & 31), jg = t >> 5;
    const float* P = Pspa + d * HID * HID;
    float acc[8];
#pragma unroll
    for (int j = 0; j < 8; ++j) acc[j] = 0.f;
    float cb = 0.f;
    for (int i = 0; i < HID; ++i) {
        float p = P[i * HID + o];
#pragma unroll
        for (int j = 0; j < 8; ++j) acc[j] += sW1[(jg * 8 + j) * HID + i] * p;
        if (jg == 0) cb += sb1[i] * p;
    }
    float* q = g_QT + d * (DIN * HID) + o * DIN + jg * 8;
    *(float4*)q = make_float4(acc[0], acc[1], acc[2], acc[3]);
    *(float4*)(q + 4) = make_float4(acc[4], acc[5], acc[6], acc[7]);
    if (jg == 0) g_CB[d * HID + o] = cb + Bspa[d * HID + o];
}

// ---------------- K0b: transpose Ptem per-d ---------------------------------
__global__ void k_tr(const float* __restrict__ Ptem) {
    __shared__ float s[32][33];
    int d = blockIdx.z;
    const float* src = Ptem + d * HID * HID;
    float* dst = g_PtemT + d * HID * HID;
    int x0 = blockIdx.x * 32, y0 = blockIdx.y * 32;
    int tx = threadIdx.x;
    for (int yy = threadIdx.y; yy < 32; yy += 8)
        s[yy][tx] = src[(y0 + yy) * HID + x0 + tx];
    __syncthreads();
    for (int yy = threadIdx.y; yy < 32; yy += 8)
        dst[(x0 + yy) * HID + y0 + tx] = s[tx][yy];
}

// ---------------- K1: WcT (bf16 hi/lo). grid (32 row-groups, 8 chunks) ------
// Loop order: accumulate 16 rows, stream P one float4 per d. regs ~80.
__global__ __launch_bounds__(256) void k_Wc(const float* __restrict__ node_eb) {
    __shared__ float sNe[16 * EMB];  // [n(16)][d(16)]
    int t = threadIdx.x;
    int nb = blockIdx.x, chunk = blockIdx.y;
    sNe[t] = node_eb[(nb * 16 + (t >> 4)) * EMB + (t & 15)];
    __syncthreads();
    int p4 = chunk * 256 + t;
    const float4* Q4 = (const float4*)g_QT;
    float4 a[16];
#pragma unroll
    for (int n = 0; n < 16; ++n) a[n] = make_float4(0.f, 0.f, 0.f, 0.f);
#pragma unroll
    for (int d = 0; d < EMB; ++d) {
        float4 v = Q4[d * 2048 + p4];
#pragma unroll
        for (int n = 0; n < 16; ++n) {
            float c = sNe[n * 16 + d];
            a[n].x += c * v.x; a[n].y += c * v.y;
            a[n].z += c * v.z; a[n].w += c * v.w;
        }
    }
#pragma unroll
    for (int n = 0; n < 16; ++n) {
        uint32_t l0, l1;
        uint32_t h0 = packhl(a[n].x, a[n].y, l0);
        uint32_t h1 = packhl(a[n].z, a[n].w, l1);
        size_t row = (size_t)(nb * 16 + n);
        ((uint2*)g_WcT_h)[row * 2048 + p4] = make_uint2(h0, h1);
        ((uint2*)g_WcT_l)[row * 2048 + p4] = make_uint2(l0, l1);
    }
}

// ---------------- K2: WtT (bf16 hi/lo). grid (48 row-groups, 16 chunks) -----
__global__ __launch_bounds__(256) void k_Wt(const float* __restrict__ time_eb) {
    __shared__ float sTe[16 * EMB];
    int t = threadIdx.x;
    int rb = blockIdx.x, chunk = blockIdx.y;
    sTe[t] = time_eb[(rb * 16 + (t >> 4)) * EMB + (t & 15)];
    __syncthreads();
    int p4 = chunk * 256 + t;
    const float4* P4 = (const float4*)g_PtemT;
    float4 a[16];
#pragma unroll
    for (int n = 0; n < 16; ++n) a[n] = make_float4(0.f, 0.f, 0.f, 0.f);
#pragma unroll
    for (int d = 0; d < EMB; ++d) {
        float4 v = P4[d * 4096 + p4];
#pragma unroll
        for (int n = 0; n < 16; ++n) {
            float c = sTe[n * 16 + d];
            a[n].x += c * v.x; a[n].y += c * v.y;
            a[n].z += c * v.z; a[n].w += c * v.w;
        }
    }
#pragma unroll
    for (int n = 0; n < 16; ++n) {
        uint32_t l0, l1;
        uint32_t h0 = packhl(a[n].x, a[n].y, l0);
        uint32_t h1 = packhl(a[n].z, a[n].w, l1);
        size_t row = (size_t)(rb * 16 + n);
        ((uint2*)g_WtT_h)[row * 4096 + p4] = make_uint2(h0, h1);
        ((uint2*)g_WtT_l)[row * 4096 + p4] = make_uint2(l0, l1);
    }
}

// ---------------- K3: biases -------------------------------------------------
__global__ void k_bias(const float* __restrict__ node_eb, const float* __restrict__ time_eb,
                       const float* __restrict__ Btem) {
    int t = threadIdx.x, b = blockIdx.x;
    if (b < NN) {
        float acc = 0.f;
#pragma unroll
        for (int d = 0; d < EMB; ++d) acc += node_eb[b * EMB + d] * g_CB[d * HID + t];
        g_bspa[b * HID + t] = acc;
    } else {
        int bt = b - NN;
        float acc = 0.f;
#pragma unroll
        for (int d = 0; d < EMB; ++d) acc += time_eb[bt * EMB + d] * Btem[d * HID + t];
        g_btem[bt * HID + t] = acc;
    }
}

// ---------------- K4: spatial GEMM (mma.sync bf16, 3-pass hi/lo) -------------
#define SP_A   4096
#define SP_SMEM (4096 + 65536)

__global__ __launch_bounds__(256) void k_spatial(const float* __restrict__ eb) {
    extern __shared__ char sm[];
    uint32_t sb = smem_to_u32(sm);
    const uint32_t AH = SP_A, AL = SP_A + 16384, BHo = SP_A + 32768, BLo = SP_A + 49152;
    int t = threadIdx.x, lane = t & 31, wid = t >> 5;
    int n = blockIdx.y, bt0 = blockIdx.x * 128;

    // B stage via cp.async FIRST (overlaps with A conversion below)
    {
        const uint4* Bhp = (const uint4*)(g_WcT_h + (size_t)n * (DIN * HID));
        const uint4* Blp = (const uint4*)(g_WcT_l + (size_t)n * (DIN * HID));
#pragma unroll
        for (int c = t; c < 1024; c += 256) {
            int row = c >> 3;
            unsigned off = (unsigned)(row * 128) + ((((unsigned)(c & 7)) * 16) ^ ((row & 7) << 4));
            CP16(sb + BHo + off, Bhp + c);
            CP16(sb + BLo + off, Blp + c);
        }
        CP_COMMIT();
    }
    if (t < 128) ((float*)sm)[t] = g_bspa[n * HID + t];

    // A stage: eb rows -> bf16 hi/lo, swizzled
    {
        int r = t >> 1, half = t & 1;
        const float* src = eb + ((size_t)(bt0 + r) * NN + n) * DIN + half * 32;
        unsigned xm = (unsigned)((r & 7) << 4);
        char* dh = sm + AH + r * 128;
        char* dl = sm + AL + r * 128;
#pragma unroll
        for (int g = 0; g < 4; ++g) {
            float4 v0 = *(const float4*)(src + g * 8);
            float4 v1 = *(const float4*)(src + g * 8 + 4);
            float xs[8] = {v0.x, v0.y, v0.z, v0.w, v1.x, v1.y, v1.z, v1.w};
            uint32_t hq[4], lq[4];
#pragma unroll
            for (int c = 0; c < 4; ++c) hq[c] = packhl(xs[2 * c], xs[2 * c + 1], lq[c]);
            unsigned kb = ((unsigned)((half * 32 + g * 8) * 2)) ^ xm;
            *(uint4*)(dh + kb) = *(uint4*)hq;
            *(uint4*)(dl + kb) = *(uint4*)lq;
        }
    }
    CP_WAIT(0);
    __syncthreads();

    float acc[2][8][4];
#pragma unroll
    for (int i = 0; i < 2; ++i)
#pragma unroll
        for (int j = 0; j < 8; ++j)
#pragma unroll
            for (int k = 0; k < 4; ++k) acc[i][j][k] = 0.f;

    int wm = wid & 3, wn = wid >> 2;
    uint32_t aB[2] = {sb + AH, sb + AL};
    uint32_t bB[2] = {sb + BHo, sb + BLo};
    const int PA[3] = {0, 0, 1}, PB[3] = {0, 1, 0};
    int arow = wm * 32 + (lane & 15);
    int brow = wn * 64 + (lane & 15);
    unsigned c16 = (unsigned)((lane >> 4) * 16);
#pragma unroll
    for (int p = 0; p < 3; ++p) {
        uint32_t ab = aB[PA[p]], bb = bB[PB[p]];
#pragma unroll
        for (int ks = 0; ks < 4; ++ks) {
            unsigned kb = (unsigned)(ks * 32);
            uint32_t af[2][4];
#pragma unroll
            for (int mf = 0; mf < 2; ++mf) {
                int row = arow + mf * 16;
                uint32_t addr = ab + row * 128 + ((kb + c16) ^ ((row & 7) << 4));
                ldsm4(af[mf][0], af[mf][1], af[mf][2], af[mf][3], addr);
            }
#pragma unroll
            for (int nq = 0; nq < 4; ++nq) {
                int row = brow + nq * 16;
                uint32_t addr = bb + row * 128 + ((kb + c16) ^ ((row & 7) << 4));
                uint32_t b0, b1, b2, b3;
                ldsm4(b0, b1, b2, b3, addr);
                mma16816(acc[0][nq * 2],     af[0][0], af[0][1], af[0][2], af[0][3], b0, b2);
                mma16816(acc[0][nq * 2 + 1], af[0][0], af[0][1], af[0][2], af[0][3], b1, b3);
                mma16816(acc[1][nq * 2],     af[1][0], af[1][1], af[1][2], af[1][3], b0, b2);
                mma16816(acc[1][nq * 2 + 1], af[1][0], af[1][1], af[1][2], af[1][3], b1, b3);
            }
        }
    }
    __syncthreads();
    // epilogue: bias+LReLU, hi/lo bf16 into smem
    {
        int qr = lane >> 2, qc = lane & 3;
#pragma unroll
        for (int mf = 0; mf < 2; ++mf) {
#pragma unroll
            for (int nf = 0; nf < 8; ++nf) {
                int c0 = wn * 64 + nf * 8 + qc * 2;
                float bi0 = ((float*)sm)[c0], bi1 = ((float*)sm)[c0 + 1];
                int m0 = wm * 32 + mf * 16 + qr;
                uint32_t l0, l1;
                uint32_t h0 = packhl(lrelu(acc[mf][nf][0] + bi0), lrelu(acc[mf][nf][1] + bi1), l0);
                uint32_t h1 = packhl(lrelu(acc[mf][nf][2] + bi0), lrelu(acc[mf][nf][3] + bi1), l1);
                unsigned o0 = (unsigned)(m0 * 256) + (((unsigned)(c0 * 2)) ^ ((m0 & 7) << 5));
                int m1 = m0 + 8;
                unsigned o1 = (unsigned)(m1 * 256) + (((unsigned)(c0 * 2)) ^ ((m1 & 7) << 5));
                *(uint32_t*)(sm + AH + o0) = h0;
                *(uint32_t*)(sm + BHo + o0) = l0;
                *(uint32_t*)(sm + AH + o1) = h1;
                *(uint32_t*)(sm + BHo + o1) = l1;
            }
        }
    }
    __syncthreads();
#pragma unroll
    for (int u = t; u < 2048; u += 256) {
        int row = u >> 4;
        unsigned o16 = (unsigned)((u & 15) * 16);
        unsigned off = (unsigned)(row * 256) + (o16 ^ ((row & 7) << 5));
        uint4 vh = *(uint4*)(sm + AH + off);
        uint4 vl = *(uint4*)(sm + BHo + off);
        size_t g = ((size_t)(bt0 + row) * NN + n) * HID + (u & 15) * 8;
        *(uint4*)(g_osp_h + g) = vh;
        *(uint4*)(g_osp_l + g) = vl;
    }
}

// ---------------- K5: temporal GEMM, persistent per-bt -----------------------
// One block per bt. B (WtT hi/lo, 64KB) resident; A (osp) streamed in 4 chunks
// of 128 rows via 2-stage cp.async pipeline. smem: 4K head + 2x64K A + 64K B.
#define TP_A    4096
#define TP_BH   (4096 + 131072)
#define TP_BL   (4096 + 131072 + 32768)
#define TP_SMEM (4096 + 196608)

__global__ __launch_bounds__(256) void k_temporal(const float* __restrict__ W3,
                                                  const float* __restrict__ b3,
                                                  float* __restrict__ out) {
    extern __shared__ char sm[];
    uint32_t sb = smem_to_u32(sm);
    int t = threadIdx.x, lane = t & 31, wid = t >> 5;
    int bt = blockIdx.x;

    // B loads (part of group 0)
    {
        const uint4* Bhp = (const uint4*)(g_WtT_h + (size_t)bt * (HID * HID));
        const uint4* Blp = (const uint4*)(g_WtT_l + (size_t)bt * (HID * HID));
#pragma unroll
        for (int u = t; u < 2048; u += 256) {
            int row = u >> 4, q = u & 15;
            unsigned off = (unsigned)((q >> 3) * 16384) + (unsigned)(row * 128) +
                           ((((unsigned)(q & 7)) * 16) ^ ((row & 7) << 4));
            CP16(sb + TP_BH + off, Bhp + u);
            CP16(sb + TP_BL + off, Blp + u);
        }
    }
    // A chunk issue helper
    auto issueA = [&](int ch, int stage) {
        const uint4* Ahp = (const uint4*)(g_osp_h + ((size_t)bt * NN + ch * 128) * HID);
        const uint4* Alp = (const uint4*)(g_osp_l + ((size_t)bt * NN + ch * 128) * HID);
        uint32_t base = sb + TP_A + stage * 65536;
#pragma unroll
        for (int u = t; u < 2048; u += 256) {
            int row = u >> 4, q = u & 15;
            unsigned off = (unsigned)((q >> 3) * 16384) + (unsigned)(row * 128) +
                           ((((unsigned)(q & 7)) * 16) ^ ((row & 7) << 4));
            CP16(base + off, Ahp + u);
            CP16(base + 32768 + off, Alp + u);
        }
        CP_COMMIT();
    };
    issueA(0, 0);  // group 0 = B + A0
    issueA(1, 1);  // group 1 = A1
    if (t < 128) ((float*)sm)[t] = g_btem[bt * HID + t];
    if (t < 64) ((float4*)(sm + 512))[t] = ((const float4*)W3)[t];

    int wm = wid & 3, wn = wid >> 2;
    const int PA[3] = {0, 0, 1}, PB[3] = {0, 1, 0};
    int arow = wm * 32 + (lane & 15);
    int brow = wn * 64 + (lane & 15);
    unsigned c16 = (unsigned)((lane >> 4) * 16);
    int qr = lane >> 2, qc = lane & 3;

    for (int ch = 0; ch < 4; ++ch) {
        if (ch == 3) { CP_WAIT(0); } else { CP_WAIT(1); }
        __syncthreads();

        float acc[2][8][4];
#pragma unroll
        for (int i = 0; i < 2; ++i)
#pragma unroll
            for (int j = 0; j < 8; ++j)
#pragma unroll
                for (int k = 0; k < 4; ++k) acc[i][j][k] = 0.f;

        uint32_t stbase = sb + TP_A + (ch & 1) * 65536;
#pragma unroll
        for (int p = 0; p < 3; ++p) {
#pragma unroll
            for (int kc = 0; kc < 2; ++kc) {
                uint32_t ab = stbase + PA[p] * 32768 + kc * 16384;
                uint32_t bb = sb + TP_BH + PB[p] * 32768 + kc * 16384;
#pragma unroll
                for (int ks = 0; ks < 4; ++ks) {
                    unsigned kb = (unsigned)(ks * 32);
                    uint32_t af[2][4];
#pragma unroll
                    for (int mf = 0; mf < 2; ++mf) {
                        int row = arow + mf * 16;
                        uint32_t addr = ab + row * 128 + ((kb + c16) ^ ((row & 7) << 4));
                        ldsm4(af[mf][0], af[mf][1], af[mf][2], af[mf][3], addr);
                    }
#pragma unroll
                    for (int nq = 0; nq < 4; ++nq) {
                        int row = brow + nq * 16;
                        uint32_t addr = bb + row * 128 + ((kb + c16) ^ ((row & 7) << 4));
                        uint32_t b0, b1, b2, b3;
                        ldsm4(b0, b1, b2, b3, addr);
                        mma16816(acc[0][nq * 2],     af[0][0], af[0][1], af[0][2], af[0][3], b0, b2);
                        mma16816(acc[0][nq * 2 + 1], af[0][0], af[0][1], af[0][2], af[0][3], b1, b3);
                        mma16816(acc[1][nq * 2],     af[1][0], af[1][1], af[1][2], af[1][3], b0, b2);
                        mma16816(acc[1][nq * 2 + 1], af[1][0], af[1][1], af[1][2], af[1][3], b1, b3);
                    }
                }
            }
        }
        __syncthreads();                 // all warps done reading this stage
        if (ch + 2 < 4) issueA(ch + 2, ch & 1);
        ((float*)(sm + 1536))[t] = 0.f;  // zero row sums [128][2]
        __syncthreads();

        // epilogue for this chunk: bias+LReLU, project via W3, reduce
        {
            const float* bias = (const float*)sm;
            const float* w3s = (const float*)(sm + 512);
            float s0[4] = {0.f, 0.f, 0.f, 0.f}, s1[4] = {0.f, 0.f, 0.f, 0.f};
#pragma unroll
            for (int mf = 0; mf < 2; ++mf) {
#pragma unroll
                for (int nf = 0; nf < 8; ++nf) {
                    int c0 = wn * 64 + nf * 8 + qc * 2;
                    float bi0 = bias[c0], bi1 = bias[c0 + 1];
                    float w00 = w3s[c0 * 2], w01 = w3s[c0 * 2 + 1];
                    float w10 = w3s[c0 * 2 + 2], w11 = w3s[c0 * 2 + 3];
                    float y00 = lrelu(acc[mf][nf][0] + bi0);
                    float y01 = lrelu(acc[mf][nf][1] + bi1);
                    float y10 = lrelu(acc[mf][nf][2] + bi0);
                    float y11 = lrelu(acc[mf][nf][3] + bi1);
                    s0[mf * 2 + 0] += y00 * w00 + y01 * w10;
                    s1[mf * 2 + 0] += y00 * w01 + y01 * w11;
                    s0[mf * 2 + 1] += y10 * w00 + y11 * w10;
                    s1[mf * 2 + 1] += y10 * w01 + y11 * w11;
                }
            }
            float* sums = (float*)(sm + 1536);
#pragma unroll
            for (int i = 0; i < 4; ++i) {
                float v0 = s0[i], v1 = s1[i];
                v0 += __shfl_xor_sync(0xffffffffu, v0, 1);
                v0 += __shfl_xor_sync(0xffffffffu, v0, 2);
                v1 += __shfl_xor_sync(0xffffffffu, v1, 1);
                v1 += __shfl_xor_sync(0xffffffffu, v1, 2);
                if (qc == 0) {
                    int row = wm * 32 + (i >> 1) * 16 + qr + (i & 1) * 8;
                    atomicAdd(sums + row * 2, v0);
                    atomicAdd(sums + row * 2 + 1, v1);
                }
            }
        }
        __syncthreads();
        if (t < 128) {
            const float* sums = (const float*)(sm + 1536);
            float2 o;
            o.x = sums[t * 2] + __ldg(b3);
            o.y = sums[t * 2 + 1] + __ldg(b3 + 1);
            *(float2*)(out + ((size_t)bt * NN + ch * 128 + t) * 2) = o;
        }
        // next iteration's post-mainloop __syncthreads orders sums reuse
    }
}

// ---------------- launch ----------------
extern "C" void kernel_launch(void* const* d_in, const int* in_sizes, int n_in,
                              void* d_out, int out_size) {
    const float* eb      = (const float*)d_in[0];
    const float* time_eb = (const float*)d_in[1];
    const float* node_eb = (const float*)d_in[2];
    const float* W1      = (const float*)d_in[3];
    const float* b1      = (const float*)d_in[4];
    const float* W3      = (const float*)d_in[5];
    const float* b3      = (const float*)d_in[6];
    const float* Pspa    = (const float*)d_in[7];
    const float* Bspa    = (const float*)d_in[8];
    const float* Ptem    = (const float*)d_in[9];
    const float* Btem    = (const float*)d_in[10];
    float* out = (float*)d_out;

    cudaFuncSetAttribute(k_spatial, cudaFuncAttributeMaxDynamicSharedMemorySize, SP_SMEM);
    cudaFuncSetAttribute(k_temporal, cudaFuncAttributeMaxDynamicSharedMemorySize, TP_SMEM);

    k_Q<<<dim3(EMB, 4), 256>>>(W1, b1, Pspa, Bspa);
    k_tr<<<dim3(4, 4, EMB), dim3(32, 8)>>>(Ptem);
    k_Wc<<<dim3(32, 8), 256>>>(node_eb);
    k_Wt<<<dim3(48, 16), 256>>>(time_eb);
    k_bias<<<NN + BT, 128>>>(node_eb, time_eb, Btem);
    k_spatial<<<dim3(6, NN), 256, SP_SMEM>>>(eb);
    k_temporal<<<BT, 256, TP_SMEM>>>(W3, b3, out);
}

// round 15
// speedup vs baseline: 1.6262x; 1.0806x over previous
#include <cuda_runtime.h>
#include <cuda_bf16.h>
#include <cstdint>

// Shapes (fixed)
#define BT   768
#define NN   512
#define DIN  64
#define HID  128
#define EMB  16

// ---------------- device-global scratch (no runtime allocs) ----------------
__device__ float g_QT[EMB * DIN * HID];     // QT[d][o*64+j] = (W1@Pspa[d])[j][o]
__device__ float g_CB[EMB * HID];
__device__ float g_PtemT[EMB * HID * HID];  // PtemT[d][o][i]
__device__ __nv_bfloat16 g_WcT_h[(size_t)NN * DIN * HID];   // [n][o][k]
__device__ __nv_bfloat16 g_WcT_l[(size_t)NN * DIN * HID];
__device__ __nv_bfloat16 g_WtT_h[(size_t)BT * HID * HID];   // [bt][o][i]
__device__ __nv_bfloat16 g_WtT_l[(size_t)BT * HID * HID];
__device__ float g_bspa[NN * HID];
__device__ float g_btem[BT * HID];
__device__ __nv_bfloat16 g_osp_h[(size_t)BT * NN * HID];    // [bt][n][o]
__device__ __nv_bfloat16 g_osp_l[(size_t)BT * NN * HID];

__device__ __forceinline__ float lrelu(float x) { return x >= 0.0f ? x : 0.01f * x; }

__device__ __forceinline__ uint32_t smem_to_u32(const void* p) {
    uint32_t a;
    asm("{ .reg .u64 t; cvta.to.shared.u64 t, %1; cvt.u32.u64 %0, t; }" : "=r"(a) : "l"(p));
    return a;
}
__device__ __forceinline__ void ldsm4(uint32_t& r0, uint32_t& r1, uint32_t& r2, uint32_t& r3,
                                      uint32_t a) {
    asm volatile("ldmatrix.sync.aligned.m8n8.x4.shared.b16 {%0,%1,%2,%3}, [%4];"
                 : "=r"(r0), "=r"(r1), "=r"(r2), "=r"(r3) : "r"(a));
}
__device__ __forceinline__ void mma16816(float* d, uint32_t a0, uint32_t a1, uint32_t a2,
                                         uint32_t a3, uint32_t b0, uint32_t b1) {
    asm volatile(
        "mma.sync.aligned.m16n8k16.row.col.f32.bf16.bf16.f32 "
        "{%0,%1,%2,%3}, {%4,%5,%6,%7}, {%8,%9}, {%0,%1,%2,%3};"
        : "+f"(d[0]), "+f"(d[1]), "+f"(d[2]), "+f"(d[3])
        : "r"(a0), "r"(a1), "r"(a2), "r"(a3), "r"(b0), "r"(b1));
}
__device__ __forceinline__ uint32_t packhl(float y0, float y1, uint32_t& lo) {
    __nv_bfloat16 h0 = __float2bfloat16(y0), h1 = __float2bfloat16(y1);
    lo = (uint32_t)__bfloat16_as_ushort(__float2bfloat16(y0 - __bfloat162float(h0))) |
         ((uint32_t)__bfloat16_as_ushort(__float2bfloat16(y1 - __bfloat162float(h1))) << 16);
    return (uint32_t)__bfloat16_as_ushort(h0) | ((uint32_t)__bfloat16_as_ushort(h1) << 16);
}

// cp.async helpers
#define CP16(dst, src) \
    asm volatile("cp.async.cg.shared.global [%0], [%1], 16;" \
                 :: "r"((uint32_t)(dst)), "l"((const void*)(src)) : "memory")
#define CP_COMMIT() asm volatile("cp.async.commit_group;" ::: "memory")
#define CP_WAIT(n)  asm volatile("cp.async.wait_group %0;" :: "n"(n) : "memory")

// ---------------- K0: QT[d] = (W1 @ Pspa[d])^T, CB[d] -----------------------
__global__ __launch_bounds__(256) void k_Q(const float* __restrict__ W1,
                                           const float* __restrict__ b1,
                                           const float* __restrict__ Pspa,
                                           const float* __restrict__ Bspa) {
    __shared__ float sW1[DIN * HID];
    __shared__ float sb1[HID];
    int t = threadIdx.x;
    for (int l = t; l < DIN * HID; l += 256) sW1[l] = W1[l];
    if (t < HID) sb1[t] = b1[t];
    __syncthreads();
    int d = blockIdx.x, oc = blockIdx.y;
    int o = oc * 32 + (t & 31), jg = t >> 5;
    const float* P = Pspa + d * HID * HID;
    float acc[8];
#pragma unroll
    for (int j = 0; j < 8; ++j) acc[j] = 0.f;
    float cb = 0.f;
    for (int i = 0; i < HID; ++i) {
        float p = P[i * HID + o];
#pragma unroll
        for (int j = 0; j < 8; ++j) acc[j] += sW1[(jg * 8 + j) * HID + i] * p;
        if (jg == 0) cb += sb1[i] * p;
    }
    float* q = g_QT + d * (DIN * HID) + o * DIN + jg * 8;
    *(float4*)q = make_float4(acc[0], acc[1], acc[2], acc[3]);
    *(float4*)(q + 4) = make_float4(acc[4], acc[5], acc[6], acc[7]);
    if (jg == 0) g_CB[d * HID + o] = cb + Bspa[d * HID + o];
}

// ---------------- K0b: transpose Ptem per-d ---------------------------------
__global__ void k_tr(const float* __restrict__ Ptem) {
    __shared__ float s[32][33];
    int d = blockIdx.z;
    const float* src = Ptem + d * HID * HID;
    float* dst = g_PtemT + d * HID * HID;
    int x0 = blockIdx.x * 32, y0 = blockIdx.y * 32;
    int tx = threadIdx.x;
    for (int yy = threadIdx.y; yy < 32; yy += 8)
        s[yy][tx] = src[(y0 + yy) * HID + x0 + tx];
    __syncthreads();
    for (int yy = threadIdx.y; yy < 32; yy += 8)
        dst[(x0 + yy) * HID + y0 + tx] = s[tx][yy];
}

// ---------------- K1: WcT (bf16 hi/lo). grid (64 row-groups, 8 chunks) ------
// 8 rows per block -> a[8] float4 = 32 acc regs, high occupancy.
__global__ __launch_bounds__(256) void k_Wc(const float* __restrict__ node_eb) {
    __shared__ float sNe[8 * EMB];  // [n(8)][d(16)]
    int t = threadIdx.x;
    int nb = blockIdx.x, chunk = blockIdx.y;
    if (t < 128) sNe[t] = node_eb[(nb * 8 + (t >> 4)) * EMB + (t & 15)];
    __syncthreads();
    int p4 = chunk * 256 + t;
    const float4* Q4 = (const float4*)g_QT;
    float4 a[8];
#pragma unroll
    for (int n = 0; n < 8; ++n) a[n] = make_float4(0.f, 0.f, 0.f, 0.f);
#pragma unroll
    for (int d = 0; d < EMB; ++d) {
        float4 v = Q4[d * 2048 + p4];
#pragma unroll
        for (int n = 0; n < 8; ++n) {
            float c = sNe[n * 16 + d];
            a[n].x += c * v.x; a[n].y += c * v.y;
            a[n].z += c * v.z; a[n].w += c * v.w;
        }
    }
#pragma unroll
    for (int n = 0; n < 8; ++n) {
        uint32_t l0, l1;
        uint32_t h0 = packhl(a[n].x, a[n].y, l0);
        uint32_t h1 = packhl(a[n].z, a[n].w, l1);
        size_t row = (size_t)(nb * 8 + n);
        ((uint2*)g_WcT_h)[row * 2048 + p4] = make_uint2(h0, h1);
        ((uint2*)g_WcT_l)[row * 2048 + p4] = make_uint2(l0, l1);
    }
}

// ---------------- K2: WtT (bf16 hi/lo). grid (96 row-groups, 16 chunks) -----
__global__ __launch_bounds__(256) void k_Wt(const float* __restrict__ time_eb) {
    __shared__ float sTe[8 * EMB];
    int t = threadIdx.x;
    int rb = blockIdx.x, chunk = blockIdx.y;
    if (t < 128) sTe[t] = time_eb[(rb * 8 + (t >> 4)) * EMB + (t & 15)];
    __syncthreads();
    int p4 = chunk * 256 + t;
    const float4* P4 = (const float4*)g_PtemT;
    float4 a[8];
#pragma unroll
    for (int n = 0; n < 8; ++n) a[n] = make_float4(0.f, 0.f, 0.f, 0.f);
#pragma unroll
    for (int d = 0; d < EMB; ++d) {
        float4 v = P4[d * 4096 + p4];
#pragma unroll
        for (int n = 0; n < 8; ++n) {
            float c = sTe[n * 16 + d];
            a[n].x += c * v.x; a[n].y += c * v.y;
            a[n].z += c * v.z; a[n].w += c * v.w;
        }
    }
#pragma unroll
    for (int n = 0; n < 8; ++n) {
        uint32_t l0, l1;
        uint32_t h0 = packhl(a[n].x, a[n].y, l0);
        uint32_t h1 = packhl(a[n].z, a[n].w, l1);
        size_t row = (size_t)(rb * 8 + n);
        ((uint2*)g_WtT_h)[row * 4096 + p4] = make_uint2(h0, h1);
        ((uint2*)g_WtT_l)[row * 4096 + p4] = make_uint2(l0, l1);
    }
}

// ---------------- K3: biases -------------------------------------------------
__global__ void k_bias(const float* __restrict__ node_eb, const float* __restrict__ time_eb,
                       const float* __restrict__ Btem) {
    int t = threadIdx.x, b = blockIdx.x;
    if (b < NN) {
        float acc = 0.f;
#pragma unroll
        for (int d = 0; d < EMB; ++d) acc += node_eb[b * EMB + d] * g_CB[d * HID + t];
        g_bspa[b * HID + t] = acc;
    } else {
        int bt = b - NN;
        float acc = 0.f;
#pragma unroll
        for (int d = 0; d < EMB; ++d) acc += time_eb[bt * EMB + d] * Btem[d * HID + t];
        g_btem[bt * HID + t] = acc;
    }
}

// ---------------- K4: spatial GEMM (mma.sync bf16, 3-pass hi/lo) -------------
#define SP_A   4096
#define SP_SMEM (4096 + 65536)

__global__ __launch_bounds__(256) void k_spatial(const float* __restrict__ eb) {
    extern __shared__ char sm[];
    uint32_t sb = smem_to_u32(sm);
    const uint32_t AH = SP_A, AL = SP_A + 16384, BHo = SP_A + 32768, BLo = SP_A + 49152;
    int t = threadIdx.x, lane = t & 31, wid = t >> 5;
    int n = blockIdx.y, bt0 = blockIdx.x * 128;

    // B stage via cp.async FIRST (overlaps with A conversion below)
    {
        const uint4* Bhp = (const uint4*)(g_WcT_h + (size_t)n * (DIN * HID));
        const uint4* Blp = (const uint4*)(g_WcT_l + (size_t)n * (DIN * HID));
#pragma unroll
        for (int c = t; c < 1024; c += 256) {
            int row = c >> 3;
            unsigned off = (unsigned)(row * 128) + ((((unsigned)(c & 7)) * 16) ^ ((row & 7) << 4));
            CP16(sb + BHo + off, Bhp + c);
            CP16(sb + BLo + off, Blp + c);
        }
        CP_COMMIT();
    }
    if (t < 128) ((float*)sm)[t] = g_bspa[n * HID + t];

    // A stage: eb rows -> bf16 hi/lo, swizzled. 8 lanes x 32B contiguous per
    // row (full 32B sectors); STS phase covers a full 128B row (conflict-free).
    {
        int s = t & 7;
#pragma unroll
        for (int pass = 0; pass < 4; ++pass) {
            int r = (t >> 3) + pass * 32;
            const float* src = eb + ((size_t)(bt0 + r) * NN + n) * DIN + s * 8;
            float4 v0 = *(const float4*)src;
            float4 v1 = *(const float4*)(src + 4);
            uint32_t hq[4], lq[4];
            hq[0] = packhl(v0.x, v0.y, lq[0]);
            hq[1] = packhl(v0.z, v0.w, lq[1]);
            hq[2] = packhl(v1.x, v1.y, lq[2]);
            hq[3] = packhl(v1.z, v1.w, lq[3]);
            unsigned kb = ((unsigned)(s * 16)) ^ ((r & 7) << 4);
            *(uint4*)(sm + AH + r * 128 + kb) = *(uint4*)hq;
            *(uint4*)(sm + AL + r * 128 + kb) = *(uint4*)lq;
        }
    }
    CP_WAIT(0);
    __syncthreads();

    float acc[2][8][4];
#pragma unroll
    for (int i = 0; i < 2; ++i)
#pragma unroll
        for (int j = 0; j < 8; ++j)
#pragma unroll
            for (int k = 0; k < 4; ++k) acc[i][j][k] = 0.f;

    int wm = wid & 3, wn = wid >> 2;
    uint32_t aB[2] = {sb + AH, sb + AL};
    uint32_t bB[2] = {sb + BHo, sb + BLo};
    const int PA[3] = {0, 0, 1}, PB[3] = {0, 1, 0};
    int arow = wm * 32 + (lane & 15);
    int brow = wn * 64 + (lane & 15);
    unsigned c16 = (unsigned)((lane >> 4) * 16);
#pragma unroll
    for (int p = 0; p < 3; ++p) {
        uint32_t ab = aB[PA[p]], bb = bB[PB[p]];
#pragma unroll
        for (int ks = 0; ks < 4; ++ks) {
            unsigned kb = (unsigned)(ks * 32);
            uint32_t af[2][4];
#pragma unroll
            for (int mf = 0; mf < 2; ++mf) {
                int row = arow + mf * 16;
                uint32_t addr = ab + row * 128 + ((kb + c16) ^ ((row & 7) << 4));
                ldsm4(af[mf][0], af[mf][1], af[mf][2], af[mf][3], addr);
            }
#pragma unroll
            for (int nq = 0; nq < 4; ++nq) {
                int row = brow + nq * 16;
                uint32_t addr = bb + row * 128 + ((kb + c16) ^ ((row & 7) << 4));
                uint32_t b0, b1, b2, b3;
                ldsm4(b0, b1, b2, b3, addr);
                mma16816(acc[0][nq * 2],     af[0][0], af[0][1], af[0][2], af[0][3], b0, b2);
                mma16816(acc[0][nq * 2 + 1], af[0][0], af[0][1], af[0][2], af[0][3], b1, b3);
                mma16816(acc[1][nq * 2],     af[1][0], af[1][1], af[1][2], af[1][3], b0, b2);
                mma16816(acc[1][nq * 2 + 1], af[1][0], af[1][1], af[1][2], af[1][3], b1, b3);
            }
        }
    }
    __syncthreads();
    // epilogue: bias+LReLU, hi/lo bf16 into smem
    {
        int qr = lane >> 2, qc = lane & 3;
#pragma unroll
        for (int mf = 0; mf < 2; ++mf) {
#pragma unroll
            for (int nf = 0; nf < 8; ++nf) {
                int c0 = wn * 64 + nf * 8 + qc * 2;
                float bi0 = ((float*)sm)[c0], bi1 = ((float*)sm)[c0 + 1];
                int m0 = wm * 32 + mf * 16 + qr;
                uint32_t l0, l1;
                uint32_t h0 = packhl(lrelu(acc[mf][nf][0] + bi0), lrelu(acc[mf][nf][1] + bi1), l0);
                uint32_t h1 = packhl(lrelu(acc[mf][nf][2] + bi0), lrelu(acc[mf][nf][3] + bi1), l1);
                unsigned o0 = (unsigned)(m0 * 256) + (((unsigned)(c0 * 2)) ^ ((m0 & 7) << 5));
                int m1 = m0 + 8;
                unsigned o1 = (unsigned)(m1 * 256) + (((unsigned)(c0 * 2)) ^ ((m1 & 7) << 5));
                *(uint32_t*)(sm + AH + o0) = h0;
                *(uint32_t*)(sm + BHo + o0) = l0;
                *(uint32_t*)(sm + AH + o1) = h1;
                *(uint32_t*)(sm + BHo + o1) = l1;
            }
        }
    }
    __syncthreads();
#pragma unroll
    for (int u = t; u < 2048; u += 256) {
        int row = u >> 4;
        unsigned o16 = (unsigned)((u & 15) * 16);
        unsigned off = (unsigned)(row * 256) + (o16 ^ ((row & 7) << 5));
        uint4 vh = *(uint4*)(sm + AH + off);
        uint4 vl = *(uint4*)(sm + BHo + off);
        size_t g = ((size_t)(bt0 + row) * NN + n) * HID + (u & 15) * 8;
        *(uint4*)(g_osp_h + g) = vh;
        *(uint4*)(g_osp_l + g) = vl;
    }
}

// ---------------- K5: temporal GEMM + LReLU + W3 projection ------------------
// R10 variant (proven faster): grid (4, BT), cp.async 2-stage over K chunks.
#define TP_A   4096
#define TP_SMEM (4096 + 131072)

__global__ __launch_bounds__(256) void k_temporal(const float* __restrict__ W3,
                                                  const float* __restrict__ b3,
                                                  float* __restrict__ out) {
    extern __shared__ char sm[];
    uint32_t sb = smem_to_u32(sm);
    const uint32_t AH = TP_A, AL = TP_A + 32768, BHo = TP_A + 65536, BLo = TP_A + 98304;
    int t = threadIdx.x, lane = t & 31, wid = t >> 5;
    int bt = blockIdx.y, n0 = blockIdx.x * 128;

    const uint4* Ahp = (const uint4*)(g_osp_h + ((size_t)bt * NN + n0) * HID);
    const uint4* Alp = (const uint4*)(g_osp_l + ((size_t)bt * NN + n0) * HID);
    const uint4* Bhp = (const uint4*)(g_WtT_h + (size_t)bt * (HID * HID));
    const uint4* Blp = (const uint4*)(g_WtT_l + (size_t)bt * (HID * HID));
#pragma unroll
    for (int ch = 0; ch < 2; ++ch) {
#pragma unroll
        for (int u = t; u < 1024; u += 256) {
            int row = u >> 3, q8 = u & 7;
            int c = row * 16 + ch * 8 + q8;
            unsigned off = (unsigned)(ch * 16384) + (unsigned)(row * 128) +
                           ((((unsigned)q8) * 16) ^ ((row & 7) << 4));
            CP16(sb + AH + off, Ahp + c);
            CP16(sb + AL + off, Alp + c);
            CP16(sb + BHo + off, Bhp + c);
            CP16(sb + BLo + off, Blp + c);
        }
        CP_COMMIT();
    }
    if (t < 128) ((float*)sm)[t] = g_btem[bt * HID + t];
    if (t < 64) ((float4*)(sm + 512))[t] = ((const float4*)W3)[t];
    ((float*)(sm + 1536))[t] = 0.f;  // row sums [128][2]

    float acc[2][8][4];
#pragma unroll
    for (int i = 0; i < 2; ++i)
#pragma unroll
        for (int j = 0; j < 8; ++j)
#pragma unroll
            for (int k = 0; k < 4; ++k) acc[i][j][k] = 0.f;

    int wm = wid & 3, wn = wid >> 2;
    uint32_t aB[2] = {sb + AH, sb + AL};
    uint32_t bB[2] = {sb + BHo, sb + BLo};
    const int PA[3] = {0, 0, 1}, PB[3] = {0, 1, 0};
    int arow = wm * 32 + (lane & 15);
    int brow = wn * 64 + (lane & 15);
    unsigned c16 = (unsigned)((lane >> 4) * 16);

#pragma unroll
    for (int ch = 0; ch < 2; ++ch) {
        if (ch == 0) { CP_WAIT(1); } else { CP_WAIT(0); }
        __syncthreads();
#pragma unroll
        for (int p = 0; p < 3; ++p) {
            uint32_t ab = aB[PA[p]] + ch * 16384, bb = bB[PB[p]] + ch * 16384;
#pragma unroll
            for (int ks = 0; ks < 4; ++ks) {
                unsigned kb = (unsigned)(ks * 32);
                uint32_t af[2][4];
#pragma unroll
                for (int mf = 0; mf < 2; ++mf) {
                    int row = arow + mf * 16;
                    uint32_t addr = ab + row * 128 + ((kb + c16) ^ ((row & 7) << 4));
                    ldsm4(af[mf][0], af[mf][1], af[mf][2], af[mf][3], addr);
                }
#pragma unroll
                for (int nq = 0; nq < 4; ++nq) {
                    int row = brow + nq * 16;
                    uint32_t addr = bb + row * 128 + ((kb + c16) ^ ((row & 7) << 4));
                    uint32_t b0, b1, b2, b3;
                    ldsm4(b0, b1, b2, b3, addr);
                    mma16816(acc[0][nq * 2],     af[0][0], af[0][1], af[0][2], af[0][3], b0, b2);
                    mma16816(acc[0][nq * 2 + 1], af[0][0], af[0][1], af[0][2], af[0][3], b1, b3);
                    mma16816(acc[1][nq * 2],     af[1][0], af[1][1], af[1][2], af[1][3], b0, b2);
                    mma16816(acc[1][nq * 2 + 1], af[1][0], af[1][1], af[1][2], af[1][3], b1, b3);
                }
            }
        }
    }
    __syncthreads();
    // epilogue: bias+LReLU, project to 2 outputs, reduce across cols
    {
        int qr = lane >> 2, qc = lane & 3;
        const float* bias = (const float*)sm;
        const float* w3s = (const float*)(sm + 512);
        float s0[4] = {0.f, 0.f, 0.f, 0.f}, s1[4] = {0.f, 0.f, 0.f, 0.f};
#pragma unroll
        for (int mf = 0; mf < 2; ++mf) {
#pragma unroll
            for (int nf = 0; nf < 8; ++nf) {
                int c0 = wn * 64 + nf * 8 + qc * 2;
                float bi0 = bias[c0], bi1 = bias[c0 + 1];
                float w00 = w3s[c0 * 2], w01 = w3s[c0 * 2 + 1];
                float w10 = w3s[c0 * 2 + 2], w11 = w3s[c0 * 2 + 3];
                float y00 = lrelu(acc[mf][nf][0] + bi0);
                float y01 = lrelu(acc[mf][nf][1] + bi1);
                float y10 = lrelu(acc[mf][nf][2] + bi0);
                float y11 = lrelu(acc[mf][nf][3] + bi1);
                s0[mf * 2 + 0] += y00 * w00 + y01 * w10;
                s1[mf * 2 + 0] += y00 * w01 + y01 * w11;
                s0[mf * 2 + 1] += y10 * w00 + y11 * w10;
                s1[mf * 2 + 1] += y10 * w01 + y11 * w11;
            }
        }
        float* sums = (float*)(sm + 1536);
#pragma unroll
        for (int i = 0; i < 4; ++i) {
            float v0 = s0[i], v1 = s1[i];
            v0 += __shfl_xor_sync(0xffffffffu, v0, 1);
            v0 += __shfl_xor_sync(0xffffffffu, v0, 2);
            v1 += __shfl_xor_sync(0xffffffffu, v1, 1);
            v1 += __shfl_xor_sync(0xffffffffu, v1, 2);
            if (qc == 0) {
                int row = wm * 32 + (i >> 1) * 16 + qr + (i & 1) * 8;
                atomicAdd(sums + row * 2, v0);
                atomicAdd(sums + row * 2 + 1, v1);
            }
        }
    }
    __syncthreads();
    if (t < 128) {
        const float* sums = (const float*)(sm + 1536);
        float2 o;
        o.x = sums[t * 2] + __ldg(b3);
        o.y = sums[t * 2 + 1] + __ldg(b3 + 1);
        *(float2*)(out + ((size_t)bt * NN + n0 + t) * 2) = o;
    }
}

// ---------------- launch ----------------
extern "C" void kernel_launch(void* const* d_in, const int* in_sizes, int n_in,
                              void* d_out, int out_size) {
    const float* eb      = (const float*)d_in[0];
    const float* time_eb = (const float*)d_in[1];
    const float* node_eb = (const float*)d_in[2];
    const float* W1      = (const float*)d_in[3];
    const float* b1      = (const float*)d_in[4];
    const float* W3      = (const float*)d_in[5];
    const float* b3      = (const float*)d_in[6];
    const float* Pspa    = (const float*)d_in[7];
    const float* Bspa    = (const float*)d_in[8];
    const float* Ptem    = (const float*)d_in[9];
    const float* Btem    = (const float*)d_in[10];
    float* out = (float*)d_out;

    cudaFuncSetAttribute(k_spatial, cudaFuncAttributeMaxDynamicSharedMemorySize, SP_SMEM);
    cudaFuncSetAttribute(k_temporal, cudaFuncAttributeMaxDynamicSharedMemorySize, TP_SMEM);

    k_Q<<<dim3(EMB, 4), 256>>>(W1, b1, Pspa, Bspa);
    k_tr<<<dim3(4, 4, EMB), dim3(32, 8)>>>(Ptem);
    k_Wc<<<dim3(64, 8), 256>>>(node_eb);
    k_Wt<<<dim3(96, 16), 256>>>(time_eb);
    k_bias<<<NN + BT, 128>>>(node_eb, time_eb, Btem);
    k_spatial<<<dim3(6, NN), 256, SP_SMEM>>>(eb);
    k_temporal<<<dim3(4, BT), 256, TP_SMEM>>>(W3, b3, out);
}